// round 1
// baseline (speedup 1.0000x reference)
#include <cuda_runtime.h>
#include <cuda_bf16.h>
#include <math_constants.h>

// Problem constants
#define BATCH 4
#define CCH   256
#define NPIX  4096      // 64*64
#define NGRP  32
#define CPG   8         // channels per group
#define GN_ELEMS (CPG * NPIX)  // 32768 per (b,g)
#define SCALE 0.0625f   // 256^-0.5
#define INV_SQRT2 0.70710678118654752f

// ---------------- scratch (device globals; no allocation allowed) ----------
__device__ float g_hs [BATCH * NPIX * CCH];          // [B,N,C] normalized input
__device__ float g_q  [BATCH * NPIX * CCH];
__device__ float g_k  [BATCH * NPIX * CCH];
__device__ float g_v  [BATCH * NPIX * CCH];
__device__ float g_s  [(long)BATCH * NPIX * NPIX];   // 268 MB attention logits/probs
__device__ float g_ao [BATCH * NPIX * CCH];          // attn @ V
__device__ float g_tmp[BATCH * NPIX * CCH];          // after Wo proj
__device__ float g_mean[BATCH * NGRP];
__device__ float g_rstd[BATCH * NGRP];

// ---------------- GroupNorm statistics ------------------------------------
__global__ void gn_stats(const float* __restrict__ x) {
    int bg = blockIdx.x;                       // b*NGRP + g
    const float* px = x + (long)bg * GN_ELEMS; // groups are contiguous channel slabs
    int tid = threadIdx.x;
    float s = 0.f, ss = 0.f;
    for (int i = tid; i < GN_ELEMS; i += 256) {
        float v = px[i];
        s += v; ss += v * v;
    }
    // warp reduce
    for (int o = 16; o; o >>= 1) {
        s  += __shfl_xor_sync(0xffffffffu, s, o);
        ss += __shfl_xor_sync(0xffffffffu, ss, o);
    }
    __shared__ float sm_s[8], sm_ss[8];
    int lane = tid & 31, warp = tid >> 5;
    if (lane == 0) { sm_s[warp] = s; sm_ss[warp] = ss; }
    __syncthreads();
    if (tid == 0) {
        float ts = 0.f, tss = 0.f;
        for (int i = 0; i < 8; i++) { ts += sm_s[i]; tss += sm_ss[i]; }
        float mean = ts * (1.0f / GN_ELEMS);
        float var  = tss * (1.0f / GN_ELEMS) - mean * mean;
        g_mean[bg] = mean;
        g_rstd[bg] = rsqrtf(var + 1e-6f);
    }
}

// ---------------- GroupNorm apply + transpose to [B,N,C] -------------------
// grid (NPIX/32, CCH/32, BATCH), block (32,8)
__global__ void gn_apply(const float* __restrict__ x,
                         const float* __restrict__ w,
                         const float* __restrict__ b,
                         float* __restrict__ hs) {
    __shared__ float tile[32][33];
    int bb = blockIdx.z, c0 = blockIdx.y * 32, n0 = blockIdx.x * 32;
    int tx = threadIdx.x, ty = threadIdx.y;
#pragma unroll
    for (int i = 0; i < 4; i++) {
        int c = c0 + ty + i * 8;
        int n = n0 + tx;
        float v = x[((long)bb * CCH + c) * NPIX + n];
        int g = c >> 3;
        v = (v - g_mean[bb * NGRP + g]) * g_rstd[bb * NGRP + g] * w[c] + b[c];
        tile[ty + i * 8][tx] = v;          // tile[cLocal][nLocal]
    }
    __syncthreads();
#pragma unroll
    for (int i = 0; i < 4; i++) {
        int n = n0 + ty + i * 8;
        int c = c0 + tx;
        hs[((long)bb * NPIX + n) * CCH + c] = tile[tx][ty + i * 8];
    }
}

// ---------------- SGEMM: C[M,N] = A[M,K] * B(') + bias ---------------------
// BT=true : B is [N,K] row-major (computes A @ B^T)
// BT=false: B is [K,N] row-major (computes A @ B)
// 128x128x16 tile, 256 threads, 8x8 microtile.
#define BM 128
#define BN 128
#define BK 16

template <bool BT>
__global__ void __launch_bounds__(256, 2)
sgemm(const float* __restrict__ A, const float* __restrict__ Bm,
      const float* __restrict__ bias, float* __restrict__ C,
      int M, int N, int K, long sA, long sB, long sC) {
    int bz = blockIdx.z;
    A  += bz * sA;
    Bm += bz * sB;
    C  += bz * sC;
    int tm = blockIdx.y * BM;
    int tn = blockIdx.x * BN;

    __shared__ float As[BK][BM + 4];
    __shared__ float Bs[BK][BN + 4];

    int tid  = threadIdx.x;
    int lane = tid & 31, warp = tid >> 5;
    int warpM = warp & 3, warpN = warp >> 2;     // 4 x 2 warps
    int m0 = warpM * 32 + (lane & 3) * 8;        // lane grid 4(m) x 8(n)
    int n0 = warpN * 64 + (lane >> 2) * 8;

    float acc[8][8];
#pragma unroll
    for (int i = 0; i < 8; i++)
#pragma unroll
        for (int j = 0; j < 8; j++) acc[i][j] = 0.f;

    for (int kt = 0; kt < K; kt += BK) {
        // A tile: [BM rows][BK k], stored transposed As[k][m]
#pragma unroll
        for (int i = 0; i < 2; i++) {
            int idx = tid + i * 256;
            int m = idx >> 2, k4 = (idx & 3) * 4;
            float4 v = *(const float4*)&A[(long)(tm + m) * K + kt + k4];
            As[k4 + 0][m] = v.x; As[k4 + 1][m] = v.y;
            As[k4 + 2][m] = v.z; As[k4 + 3][m] = v.w;
        }
        if (BT) {
#pragma unroll
            for (int i = 0; i < 2; i++) {
                int idx = tid + i * 256;
                int n = idx >> 2, k4 = (idx & 3) * 4;
                float4 v = *(const float4*)&Bm[(long)(tn + n) * K + kt + k4];
                Bs[k4 + 0][n] = v.x; Bs[k4 + 1][n] = v.y;
                Bs[k4 + 2][n] = v.z; Bs[k4 + 3][n] = v.w;
            }
        } else {
#pragma unroll
            for (int i = 0; i < 2; i++) {
                int idx = tid + i * 256;
                int k = idx >> 5, n4 = (idx & 31) * 4;
                float4 v = *(const float4*)&Bm[(long)(kt + k) * N + tn + n4];
                *(float4*)&Bs[k][n4] = v;
            }
        }
        __syncthreads();
#pragma unroll
        for (int kk = 0; kk < BK; kk++) {
            float a[8], b[8];
            *(float4*)(a)     = *(float4*)&As[kk][m0];
            *(float4*)(a + 4) = *(float4*)&As[kk][m0 + 4];
            *(float4*)(b)     = *(float4*)&Bs[kk][n0];
            *(float4*)(b + 4) = *(float4*)&Bs[kk][n0 + 4];
#pragma unroll
            for (int i = 0; i < 8; i++)
#pragma unroll
                for (int j = 0; j < 8; j++) acc[i][j] += a[i] * b[j];
        }
        __syncthreads();
    }

    float bb[8];
#pragma unroll
    for (int j = 0; j < 8; j++) bb[j] = bias ? bias[tn + n0 + j] : 0.f;

#pragma unroll
    for (int i = 0; i < 8; i++) {
        long crow = (long)(tm + m0 + i) * N + tn + n0;
        float4 v0, v1;
        v0.x = acc[i][0] + bb[0]; v0.y = acc[i][1] + bb[1];
        v0.z = acc[i][2] + bb[2]; v0.w = acc[i][3] + bb[3];
        v1.x = acc[i][4] + bb[4]; v1.y = acc[i][5] + bb[5];
        v1.z = acc[i][6] + bb[6]; v1.w = acc[i][7] + bb[7];
        *(float4*)&C[crow]     = v0;
        *(float4*)&C[crow + 4] = v1;
    }
}

// ---------------- row softmax (4096 wide, in-place, logits * SCALE) --------
__global__ void softmax_rows(float* __restrict__ S) {
    long row = blockIdx.x;
    float* p = S + row * (long)NPIX;
    int tid = threadIdx.x;
    float vals[16];
    float mx = -CUDART_INF_F;
#pragma unroll
    for (int i = 0; i < 16; i++) {
        vals[i] = p[tid + i * 256];
        mx = fmaxf(mx, vals[i]);
    }
    __shared__ float sm[8];
    for (int o = 16; o; o >>= 1) mx = fmaxf(mx, __shfl_xor_sync(0xffffffffu, mx, o));
    int lane = tid & 31, warp = tid >> 5;
    if (lane == 0) sm[warp] = mx;
    __syncthreads();
    if (warp == 0) {
        float v = sm[lane & 7];
        for (int o = 4; o; o >>= 1) v = fmaxf(v, __shfl_xor_sync(0xffffffffu, v, o));
        if (lane == 0) sm[0] = v;
    }
    __syncthreads();
    mx = sm[0];
    __syncthreads();

    float sum = 0.f;
#pragma unroll
    for (int i = 0; i < 16; i++) {
        vals[i] = __expf((vals[i] - mx) * SCALE);
        sum += vals[i];
    }
    for (int o = 16; o; o >>= 1) sum += __shfl_xor_sync(0xffffffffu, sum, o);
    if (lane == 0) sm[warp] = sum;
    __syncthreads();
    if (warp == 0) {
        float v = sm[lane & 7];
        for (int o = 4; o; o >>= 1) v += __shfl_xor_sync(0xffffffffu, v, o);
        if (lane == 0) sm[0] = v;
    }
    __syncthreads();
    float inv = 1.0f / sm[0];
#pragma unroll
    for (int i = 0; i < 16; i++) p[tid + i * 256] = vals[i] * inv;
}

// ---------------- final: y = (x + tmp^T) * 1/sqrt(2) -----------------------
// grid (NPIX/32, CCH/32, BATCH), block (32,8)
__global__ void final_residual(const float* __restrict__ x,
                               const float* __restrict__ tmp,
                               float* __restrict__ y) {
    __shared__ float tile[32][33];
    int bb = blockIdx.z, c0 = blockIdx.y * 32, n0 = blockIdx.x * 32;
    int tx = threadIdx.x, ty = threadIdx.y;
#pragma unroll
    for (int i = 0; i < 4; i++) {
        int n = n0 + ty + i * 8;
        int c = c0 + tx;
        tile[ty + i * 8][tx] = tmp[((long)bb * NPIX + n) * CCH + c]; // tile[nL][cL]
    }
    __syncthreads();
#pragma unroll
    for (int i = 0; i < 4; i++) {
        int c = c0 + ty + i * 8;
        int n = n0 + tx;
        long idx = ((long)bb * CCH + c) * NPIX + n;
        y[idx] = (x[idx] + tile[tx][ty + i * 8]) * INV_SQRT2;
    }
}

// ---------------- launch ----------------------------------------------------
extern "C" void kernel_launch(void* const* d_in, const int* in_sizes, int n_in,
                              void* d_out, int out_size) {
    const float* x  = (const float*)d_in[0];
    const float* gw = (const float*)d_in[1];
    const float* gb = (const float*)d_in[2];
    const float* Wq = (const float*)d_in[3];
    const float* bq = (const float*)d_in[4];
    const float* Wk = (const float*)d_in[5];
    const float* bk = (const float*)d_in[6];
    const float* Wv = (const float*)d_in[7];
    const float* bv = (const float*)d_in[8];
    const float* Wo = (const float*)d_in[9];
    const float* bo = (const float*)d_in[10];
    float* y = (float*)d_out;

    float *hs, *q, *k, *v, *s, *ao, *tmp;
    cudaGetSymbolAddress((void**)&hs,  g_hs);
    cudaGetSymbolAddress((void**)&q,   g_q);
    cudaGetSymbolAddress((void**)&k,   g_k);
    cudaGetSymbolAddress((void**)&v,   g_v);
    cudaGetSymbolAddress((void**)&s,   g_s);
    cudaGetSymbolAddress((void**)&ao,  g_ao);
    cudaGetSymbolAddress((void**)&tmp, g_tmp);

    const long NC = (long)NPIX * CCH;       // per-batch [N,C] stride
    const long NN = (long)NPIX * NPIX;      // per-batch [N,N] stride
    const int  MALL = BATCH * NPIX;         // 16384

    gn_stats<<<BATCH * NGRP, 256>>>(x);
    gn_apply<<<dim3(NPIX / 32, CCH / 32, BATCH), dim3(32, 8)>>>(x, gw, gb, hs);

    // QKV projections: [16384,256] @ W^T + b
    sgemm<true><<<dim3(CCH / BN, MALL / BM, 1), 256>>>(hs, Wq, bq, q, MALL, CCH, CCH, 0, 0, 0);
    sgemm<true><<<dim3(CCH / BN, MALL / BM, 1), 256>>>(hs, Wk, bk, k, MALL, CCH, CCH, 0, 0, 0);
    sgemm<true><<<dim3(CCH / BN, MALL / BM, 1), 256>>>(hs, Wv, bv, v, MALL, CCH, CCH, 0, 0, 0);

    // S = Q @ K^T, batched over 4
    sgemm<true><<<dim3(NPIX / BN, NPIX / BM, BATCH), 256>>>(q, k, nullptr, s,
                                                            NPIX, NPIX, CCH, NC, NC, NN);
    softmax_rows<<<MALL, 256>>>(s);

    // AO = P @ V, batched (K = 4096)
    sgemm<false><<<dim3(CCH / BN, NPIX / BM, BATCH), 256>>>(s, v, nullptr, ao,
                                                            NPIX, CCH, NPIX, NN, NC, NC);

    // O projection
    sgemm<true><<<dim3(CCH / BN, MALL / BM, 1), 256>>>(ao, Wo, bo, tmp, MALL, CCH, CCH, 0, 0, 0);

    // residual + transpose back + scale
    final_residual<<<dim3(NPIX / 32, CCH / 32, BATCH), dim3(32, 8)>>>(x, tmp, y);
}

// round 3
// speedup vs baseline: 1.9123x; 1.9123x over previous
#include <cuda_runtime.h>
#include <cuda_bf16.h>
#include <math_constants.h>
#include <cstdint>

typedef __nv_bfloat16 bf16;

#define BATCH 4
#define CCH   256
#define NPIX  4096
#define NGRP  32
#define GN_ELEMS (8 * NPIX)
#define SCALE 0.0625f
#define INV_SQRT2 0.70710678118654752f

#define NELT (BATCH * NPIX * CCH)            // 4,194,304
#define NNELT ((size_t)BATCH * NPIX * NPIX)  // 67,108,864

// ---------------- scratch (device globals) ---------------------------------
__device__ bf16  g_hs_h[NELT], g_hs_l[NELT];
__device__ bf16  g_q_h [NELT], g_q_l [NELT];
__device__ bf16  g_k_h [NELT], g_k_l [NELT];
__device__ float g_v   [NELT];
__device__ bf16  g_vt_h[NELT], g_vt_l[NELT];
__device__ float g_s   [NNELT];
__device__ bf16  g_p_h [NNELT], g_p_l[NNELT];
__device__ bf16  g_ao_h[NELT], g_ao_l[NELT];
__device__ float g_tmp [NELT];
__device__ bf16  g_w_h [4 * CCH * CCH], g_w_l[4 * CCH * CCH];
__device__ float g_mean[BATCH * NGRP], g_rstd[BATCH * NGRP];

// ---------------- helpers ----------------------------------------------------
__device__ __forceinline__ uint32_t smem_u32(const void* p) {
    uint32_t a;
    asm("{ .reg .u64 t; cvta.to.shared.u64 t, %1; cvt.u32.u64 %0, t; }"
        : "=r"(a) : "l"(p));
    return a;
}
__device__ __forceinline__ void cp_async16(uint32_t dst, const void* src) {
    asm volatile("cp.async.cg.shared.global [%0], [%1], 16;" :: "r"(dst), "l"(src));
}
__device__ __forceinline__ void mma16816(float* c, const uint32_t* a, const uint32_t* b) {
    asm volatile(
        "mma.sync.aligned.m16n8k16.row.col.f32.bf16.bf16.f32 "
        "{%0,%1,%2,%3}, {%4,%5,%6,%7}, {%8,%9}, {%0,%1,%2,%3};"
        : "+f"(c[0]), "+f"(c[1]), "+f"(c[2]), "+f"(c[3])
        : "r"(a[0]), "r"(a[1]), "r"(a[2]), "r"(a[3]), "r"(b[0]), "r"(b[1]));
}
__device__ __forceinline__ uint32_t pack_bf2(float f0, float f1) {
    uint32_t u0 = (__bfloat16_as_ushort(__float2bfloat16(f0)));
    uint32_t u1 = (__bfloat16_as_ushort(__float2bfloat16(f1)));
    return u0 | (u1 << 16);
}

// ---------------- GroupNorm statistics --------------------------------------
__global__ void gn_stats(const float* __restrict__ x) {
    int bg = blockIdx.x;
    const float* px = x + (size_t)bg * GN_ELEMS;
    int tid = threadIdx.x;
    float s = 0.f, ss = 0.f;
    for (int i = tid; i < GN_ELEMS; i += 256) {
        float v = px[i];
        s += v; ss += v * v;
    }
    for (int o = 16; o; o >>= 1) {
        s  += __shfl_xor_sync(0xffffffffu, s, o);
        ss += __shfl_xor_sync(0xffffffffu, ss, o);
    }
    __shared__ float sm_s[8], sm_ss[8];
    int lane = tid & 31, warp = tid >> 5;
    if (lane == 0) { sm_s[warp] = s; sm_ss[warp] = ss; }
    __syncthreads();
    if (tid == 0) {
        float ts = 0.f, tss = 0.f;
        for (int i = 0; i < 8; i++) { ts += sm_s[i]; tss += sm_ss[i]; }
        float mean = ts * (1.0f / GN_ELEMS);
        float var  = tss * (1.0f / GN_ELEMS) - mean * mean;
        g_mean[bg] = mean;
        g_rstd[bg] = rsqrtf(var + 1e-6f);
    }
}

// ---------------- GroupNorm apply + transpose + bf16 split -------------------
__global__ void gn_apply(const float* __restrict__ x,
                         const float* __restrict__ w,
                         const float* __restrict__ b,
                         bf16* __restrict__ hh, bf16* __restrict__ hl) {
    __shared__ float tile[32][33];
    int bb = blockIdx.z, c0 = blockIdx.y * 32, n0 = blockIdx.x * 32;
    int tx = threadIdx.x, ty = threadIdx.y;
#pragma unroll
    for (int i = 0; i < 4; i++) {
        int c = c0 + ty + i * 8;
        int n = n0 + tx;
        float v = x[((size_t)bb * CCH + c) * NPIX + n];
        int g = c >> 3;
        v = (v - g_mean[bb * NGRP + g]) * g_rstd[bb * NGRP + g] * w[c] + b[c];
        tile[ty + i * 8][tx] = v;
    }
    __syncthreads();
#pragma unroll
    for (int i = 0; i < 4; i++) {
        int n = n0 + ty + i * 8;
        int c = c0 + tx;
        float v = tile[tx][ty + i * 8];
        size_t idx = ((size_t)bb * NPIX + n) * CCH + c;
        bf16 h = __float2bfloat16(v);
        hh[idx] = h;
        hl[idx] = __float2bfloat16(v - __bfloat162float(h));
    }
}

// ---------------- split 4 weight matrices ------------------------------------
__global__ void split_weights(const float* __restrict__ q, const float* __restrict__ k,
                              const float* __restrict__ v, const float* __restrict__ o,
                              bf16* __restrict__ wh, bf16* __restrict__ wl) {
    int i = blockIdx.x * 256 + threadIdx.x;
    int mat = i >> 16, off = i & 65535;
    const float* src = (mat == 0) ? q : (mat == 1) ? k : (mat == 2) ? v : o;
    float val = src[off];
    bf16 h = __float2bfloat16(val);
    wh[i] = h;
    wl[i] = __float2bfloat16(val - __bfloat162float(h));
}

// ---------------- transpose+split v: [B,N,C] f32 -> [B,C,N] bf16 hi/lo -------
__global__ void v_transpose(const float* __restrict__ v,
                            bf16* __restrict__ th, bf16* __restrict__ tl) {
    __shared__ float tile[32][33];
    int bb = blockIdx.z, c0 = blockIdx.y * 32, n0 = blockIdx.x * 32;
    int tx = threadIdx.x, ty = threadIdx.y;
#pragma unroll
    for (int i = 0; i < 4; i++) {
        int n = n0 + ty + i * 8;
        tile[ty + i * 8][tx] = v[((size_t)bb * NPIX + n) * CCH + c0 + tx];
    }
    __syncthreads();
#pragma unroll
    for (int i = 0; i < 4; i++) {
        int c = c0 + ty + i * 8;
        int n = n0 + tx;
        float val = tile[tx][ty + i * 8];
        size_t idx = ((size_t)bb * CCH + c) * NPIX + n;
        bf16 h = __float2bfloat16(val);
        th[idx] = h;
        tl[idx] = __float2bfloat16(val - __bfloat162float(h));
    }
}

// ---------------- mma.sync GEMM: C = A @ B^T (+bias) -------------------------
// A [M,K] hi/lo bf16 row-major; B [N,K] hi/lo bf16 row-major.
// EMODE 0: fp32 out; EMODE 1: bf16 hi/lo out.
// 128x128x32 tile, 3-stage cp.async pipeline, 8 warps (warp tile 64x32).
// Compute (Ah+Al)@(Bh+Bl)^T ~= Ah Bh + Ah Bl + Al Bh  (fp32 accumulate).
//
// SMEM: per stage 4 operand arrays, each 128 rows x 40 bf16 (32 data + 8 pad).
// Row stride 40 elems = 20 banks -> rows 0..7 hit distinct banks for LDS.32.
#define RS     40                   // padded row stride (elems)
#define TERMSZ (128 * RS)           // 5120 elems = 10240 B
#define STAGESZ (4 * TERMSZ)        // elems per stage
#define SMEMSZ (3 * STAGESZ * 2)    // bytes = 122880

template <int EMODE>
__global__ void __launch_bounds__(256, 1)
mma_gemm(const bf16* __restrict__ Ah, const bf16* __restrict__ Al,
         const bf16* __restrict__ Bh, const bf16* __restrict__ Bl,
         const float* __restrict__ bias,
         float* __restrict__ Cf, bf16* __restrict__ Ch, bf16* __restrict__ Cl,
         int M, int N, int K, long sA, long sB, long sC) {
    extern __shared__ bf16 sm[];
    int tid = threadIdx.x, lane = tid & 31, wid = tid >> 5;
    Ah += (size_t)blockIdx.z * sA;
    Al += (size_t)blockIdx.z * sA;
    Bh += (size_t)blockIdx.z * sB;
    Bl += (size_t)blockIdx.z * sB;
    size_t coff = (size_t)blockIdx.z * sC;
    int tm = blockIdx.y * 128, tn = blockIdx.x * 128;
    int nk = K >> 5;                       // 32-wide K chunks

    int wm0 = (wid & 1) * 64;              // warp m offset in tile
    int wn0 = (wid >> 1) * 32;             // warp n offset in tile
    int gr = lane >> 2, tc = lane & 3;

    uint32_t sb = smem_u32(sm);

    float acc[4][4][4];
#pragma unroll
    for (int i = 0; i < 4; i++)
#pragma unroll
        for (int j = 0; j < 4; j++)
#pragma unroll
            for (int r = 0; r < 4; r++) acc[i][j][r] = 0.f;

    auto load_stage = [&](int chunk) {
        int st = (chunk % 3);
        int kb = chunk * 32;
#pragma unroll
        for (int i = 0; i < 8; i++) {
            int c = tid + i * 256;          // 0..2047
            int t = c >> 9;                 // term 0..3
            int idx = c & 511;
            int row = idx >> 2, g = idx & 3;
            const bf16* src = (t == 0) ? Ah : (t == 1) ? Al : (t == 2) ? Bh : Bl;
            int rb = (t < 2) ? tm : tn;
            uint32_t dst = sb + (uint32_t)(st * STAGESZ + t * TERMSZ + row * RS + g * 8) * 2;
            cp_async16(dst, src + ((size_t)(rb + row) * K + kb + g * 8));
        }
        asm volatile("cp.async.commit_group;" ::: "memory");
    };

    load_stage(0);
    if (nk > 1) load_stage(1);

    for (int kt = 0; kt < nk; kt++) {
        if (kt < nk - 1) asm volatile("cp.async.wait_group 1;" ::: "memory");
        else             asm volatile("cp.async.wait_group 0;" ::: "memory");
        __syncthreads();
        if (kt + 2 < nk) load_stage(kt + 2);

        const bf16* As_h = sm + (kt % 3) * STAGESZ;
        const bf16* As_l = As_h + TERMSZ;
        const bf16* Bs_h = As_h + 2 * TERMSZ;
        const bf16* Bs_l = As_h + 3 * TERMSZ;

#pragma unroll
        for (int kk = 0; kk < 2; kk++) {
            int k0 = kk * 16 + tc * 2;
            uint32_t ah[4][4], al[4][4], bh[4][2], bl[4][2];
#pragma unroll
            for (int mi = 0; mi < 4; mi++) {
                int r = wm0 + mi * 16 + gr;
                ah[mi][0] = *(const uint32_t*)&As_h[r * RS + k0];
                ah[mi][1] = *(const uint32_t*)&As_h[(r + 8) * RS + k0];
                ah[mi][2] = *(const uint32_t*)&As_h[r * RS + k0 + 8];
                ah[mi][3] = *(const uint32_t*)&As_h[(r + 8) * RS + k0 + 8];
                al[mi][0] = *(const uint32_t*)&As_l[r * RS + k0];
                al[mi][1] = *(const uint32_t*)&As_l[(r + 8) * RS + k0];
                al[mi][2] = *(const uint32_t*)&As_l[r * RS + k0 + 8];
                al[mi][3] = *(const uint32_t*)&As_l[(r + 8) * RS + k0 + 8];
            }
#pragma unroll
            for (int ni = 0; ni < 4; ni++) {
                int rn = wn0 + ni * 8 + gr;
                bh[ni][0] = *(const uint32_t*)&Bs_h[rn * RS + k0];
                bh[ni][1] = *(const uint32_t*)&Bs_h[rn * RS + k0 + 8];
                bl[ni][0] = *(const uint32_t*)&Bs_l[rn * RS + k0];
                bl[ni][1] = *(const uint32_t*)&Bs_l[rn * RS + k0 + 8];
            }
#pragma unroll
            for (int mi = 0; mi < 4; mi++)
#pragma unroll
                for (int ni = 0; ni < 4; ni++) {
                    mma16816(acc[mi][ni], ah[mi], bh[ni]);
                    mma16816(acc[mi][ni], ah[mi], bl[ni]);
                    mma16816(acc[mi][ni], al[mi], bh[ni]);
                }
        }
        __syncthreads();
    }

    // epilogue
#pragma unroll
    for (int mi = 0; mi < 4; mi++) {
#pragma unroll
        for (int ni = 0; ni < 4; ni++) {
            int m = tm + wm0 + mi * 16 + gr;
            int n = tn + wn0 + ni * 8 + tc * 2;
            float b0v = bias ? bias[n]     : 0.f;
            float b1v = bias ? bias[n + 1] : 0.f;
            float c0 = acc[mi][ni][0] + b0v, c1 = acc[mi][ni][1] + b1v;
            float c2 = acc[mi][ni][2] + b0v, c3 = acc[mi][ni][3] + b1v;
            if (EMODE == 0) {
                float2 v0 = {c0, c1}, v1 = {c2, c3};
                *(float2*)&Cf[coff + (size_t)m * N + n]       = v0;
                *(float2*)&Cf[coff + (size_t)(m + 8) * N + n] = v1;
            } else {
                bf16 h0 = __float2bfloat16(c0), h1 = __float2bfloat16(c1);
                bf16 h2 = __float2bfloat16(c2), h3 = __float2bfloat16(c3);
                uint32_t hi0 = (uint32_t)__bfloat16_as_ushort(h0) |
                               ((uint32_t)__bfloat16_as_ushort(h1) << 16);
                uint32_t hi1 = (uint32_t)__bfloat16_as_ushort(h2) |
                               ((uint32_t)__bfloat16_as_ushort(h3) << 16);
                uint32_t lo0 = pack_bf2(c0 - __bfloat162float(h0), c1 - __bfloat162float(h1));
                uint32_t lo1 = pack_bf2(c2 - __bfloat162float(h2), c3 - __bfloat162float(h3));
                *(uint32_t*)&Ch[coff + (size_t)m * N + n]       = hi0;
                *(uint32_t*)&Ch[coff + (size_t)(m + 8) * N + n] = hi1;
                *(uint32_t*)&Cl[coff + (size_t)m * N + n]       = lo0;
                *(uint32_t*)&Cl[coff + (size_t)(m + 8) * N + n] = lo1;
            }
        }
    }
}

// ---------------- row softmax -> bf16 hi/lo probs ----------------------------
__global__ void softmax_rows(const float* __restrict__ S,
                             bf16* __restrict__ Ph, bf16* __restrict__ Pl) {
    size_t row = blockIdx.x;
    const float* p = S + row * (size_t)NPIX;
    int tid = threadIdx.x;
    float vals[16];
    float mx = -CUDART_INF_F;
#pragma unroll
    for (int i = 0; i < 16; i++) {
        vals[i] = p[tid + i * 256];
        mx = fmaxf(mx, vals[i]);
    }
    __shared__ float sm[8];
    for (int o = 16; o; o >>= 1) mx = fmaxf(mx, __shfl_xor_sync(0xffffffffu, mx, o));
    int lane = tid & 31, warp = tid >> 5;
    if (lane == 0) sm[warp] = mx;
    __syncthreads();
    if (warp == 0) {
        float v = sm[lane & 7];
        for (int o = 4; o; o >>= 1) v = fmaxf(v, __shfl_xor_sync(0xffffffffu, v, o));
        if (lane == 0) sm[0] = v;
    }
    __syncthreads();
    mx = sm[0];
    __syncthreads();

    float sum = 0.f;
#pragma unroll
    for (int i = 0; i < 16; i++) {
        vals[i] = __expf((vals[i] - mx) * SCALE);
        sum += vals[i];
    }
    for (int o = 16; o; o >>= 1) sum += __shfl_xor_sync(0xffffffffu, sum, o);
    if (lane == 0) sm[warp] = sum;
    __syncthreads();
    if (warp == 0) {
        float v = sm[lane & 7];
        for (int o = 4; o; o >>= 1) v += __shfl_xor_sync(0xffffffffu, v, o);
        if (lane == 0) sm[0] = v;
    }
    __syncthreads();
    float inv = 1.0f / sm[0];
    size_t obase = row * (size_t)NPIX;
#pragma unroll
    for (int i = 0; i < 16; i++) {
        float pv = vals[i] * inv;
        bf16 h = __float2bfloat16(pv);
        size_t o = obase + tid + i * 256;
        Ph[o] = h;
        Pl[o] = __float2bfloat16(pv - __bfloat162float(h));
    }
}

// ---------------- final: y = (x + tmp^T) * 1/sqrt(2) -------------------------
__global__ void final_residual(const float* __restrict__ x,
                               const float* __restrict__ tmp,
                               float* __restrict__ y) {
    __shared__ float tile[32][33];
    int bb = blockIdx.z, c0 = blockIdx.y * 32, n0 = blockIdx.x * 32;
    int tx = threadIdx.x, ty = threadIdx.y;
#pragma unroll
    for (int i = 0; i < 4; i++) {
        int n = n0 + ty + i * 8;
        tile[ty + i * 8][tx] = tmp[((size_t)bb * NPIX + n) * CCH + c0 + tx];
    }
    __syncthreads();
#pragma unroll
    for (int i = 0; i < 4; i++) {
        int c = c0 + ty + i * 8;
        int n = n0 + tx;
        size_t idx = ((size_t)bb * CCH + c) * NPIX + n;
        y[idx] = (x[idx] + tile[tx][ty + i * 8]) * INV_SQRT2;
    }
}

// ---------------- launch ------------------------------------------------------
extern "C" void kernel_launch(void* const* d_in, const int* in_sizes, int n_in,
                              void* d_out, int out_size) {
    const float* x  = (const float*)d_in[0];
    const float* gw = (const float*)d_in[1];
    const float* gb = (const float*)d_in[2];
    const float* Wq = (const float*)d_in[3];
    const float* bq = (const float*)d_in[4];
    const float* Wk = (const float*)d_in[5];
    const float* bk = (const float*)d_in[6];
    const float* Wv = (const float*)d_in[7];
    const float* bv = (const float*)d_in[8];
    const float* Wo = (const float*)d_in[9];
    const float* bo = (const float*)d_in[10];
    float* y = (float*)d_out;

    cudaFuncSetAttribute(mma_gemm<0>, cudaFuncAttributeMaxDynamicSharedMemorySize, SMEMSZ);
    cudaFuncSetAttribute(mma_gemm<1>, cudaFuncAttributeMaxDynamicSharedMemorySize, SMEMSZ);

    bf16 *hs_h, *hs_l, *q_h, *q_l, *k_h, *k_l, *vt_h, *vt_l, *p_h, *p_l, *ao_h, *ao_l, *w_h, *w_l;
    float *v, *s, *tmp;
    cudaGetSymbolAddress((void**)&hs_h, g_hs_h);
    cudaGetSymbolAddress((void**)&hs_l, g_hs_l);
    cudaGetSymbolAddress((void**)&q_h,  g_q_h);
    cudaGetSymbolAddress((void**)&q_l,  g_q_l);
    cudaGetSymbolAddress((void**)&k_h,  g_k_h);
    cudaGetSymbolAddress((void**)&k_l,  g_k_l);
    cudaGetSymbolAddress((void**)&v,    g_v);
    cudaGetSymbolAddress((void**)&vt_h, g_vt_h);
    cudaGetSymbolAddress((void**)&vt_l, g_vt_l);
    cudaGetSymbolAddress((void**)&s,    g_s);
    cudaGetSymbolAddress((void**)&p_h,  g_p_h);
    cudaGetSymbolAddress((void**)&p_l,  g_p_l);
    cudaGetSymbolAddress((void**)&ao_h, g_ao_h);
    cudaGetSymbolAddress((void**)&ao_l, g_ao_l);
    cudaGetSymbolAddress((void**)&tmp,  g_tmp);
    cudaGetSymbolAddress((void**)&w_h,  g_w_h);
    cudaGetSymbolAddress((void**)&w_l,  g_w_l);

    const long NC = (long)NPIX * CCH;
    const long NN = (long)NPIX * NPIX;
    const int  MALL = BATCH * NPIX;   // 16384

    gn_stats<<<BATCH * NGRP, 256>>>(x);
    gn_apply<<<dim3(NPIX / 32, CCH / 32, BATCH), dim3(32, 8)>>>(x, gw, gb, hs_h, hs_l);
    split_weights<<<1024, 256>>>(Wq, Wk, Wv, Wo, w_h, w_l);

    // QKV projections: [16384,256] @ W^T + b
    mma_gemm<1><<<dim3(2, MALL / 128, 1), 256, SMEMSZ>>>(
        hs_h, hs_l, w_h, w_l, bq, nullptr, q_h, q_l, MALL, CCH, CCH, 0, 0, 0);
    mma_gemm<1><<<dim3(2, MALL / 128, 1), 256, SMEMSZ>>>(
        hs_h, hs_l, w_h + 65536, w_l + 65536, bk, nullptr, k_h, k_l, MALL, CCH, CCH, 0, 0, 0);
    mma_gemm<0><<<dim3(2, MALL / 128, 1), 256, SMEMSZ>>>(
        hs_h, hs_l, w_h + 131072, w_l + 131072, bv, v, nullptr, nullptr, MALL, CCH, CCH, 0, 0, 0);
    v_transpose<<<dim3(NPIX / 32, CCH / 32, BATCH), dim3(32, 8)>>>(v, vt_h, vt_l);

    // S = Q @ K^T (batched over 4)
    mma_gemm<0><<<dim3(32, 32, BATCH), 256, SMEMSZ>>>(
        q_h, q_l, k_h, k_l, nullptr, s, nullptr, nullptr, NPIX, NPIX, CCH, NC, NC, NN);

    softmax_rows<<<MALL, 256>>>(s, p_h, p_l);

    // AO = P @ V  (B operand = V^T as [C,N] K-major)
    mma_gemm<1><<<dim3(2, 32, BATCH), 256, SMEMSZ>>>(
        p_h, p_l, vt_h, vt_l, nullptr, nullptr, ao_h, ao_l, NPIX, CCH, NPIX, NN, NC, NC);

    // O projection
    mma_gemm<0><<<dim3(2, MALL / 128, 1), 256, SMEMSZ>>>(
        ao_h, ao_l, w_h + 196608, w_l + 196608, bo, tmp, nullptr, nullptr, MALL, CCH, CCH, 0, 0, 0);

    final_residual<<<dim3(NPIX / 32, CCH / 32, BATCH), dim3(32, 8)>>>(x, tmp, y);
}

// round 4
// speedup vs baseline: 2.1289x; 1.1133x over previous
#include <cuda_runtime.h>
#include <cuda_bf16.h>
#include <math_constants.h>
#include <cstdint>

typedef __nv_bfloat16 bf16;

#define BATCH 4
#define CCH   256
#define NPIX  4096
#define NGRP  32
#define GN_ELEMS (8 * NPIX)
#define SCALE 0.0625f
#define INV_SQRT2 0.70710678118654752f

#define NELT (BATCH * NPIX * CCH)            // 4,194,304
#define NNELT ((size_t)BATCH * NPIX * NPIX)  // 67,108,864

// ---------------- scratch (device globals) ---------------------------------
__device__ bf16  g_hs_h[NELT], g_hs_l[NELT];
__device__ bf16  g_q_h [NELT], g_q_l [NELT];
__device__ bf16  g_k_h [NELT], g_k_l [NELT];
__device__ float g_v   [NELT];
__device__ bf16  g_vt_h[NELT], g_vt_l[NELT];
__device__ float g_s   [NNELT];
__device__ bf16  g_p_h [NNELT], g_p_l[NNELT];
__device__ bf16  g_ao_h[NELT], g_ao_l[NELT];
__device__ float g_tmp [NELT];
__device__ bf16  g_w_h [4 * CCH * CCH], g_w_l[4 * CCH * CCH];
__device__ float g_mean[BATCH * NGRP], g_rstd[BATCH * NGRP];

// ---------------- helpers ----------------------------------------------------
__device__ __forceinline__ uint32_t smem_u32(const void* p) {
    uint32_t a;
    asm("{ .reg .u64 t; cvta.to.shared.u64 t, %1; cvt.u32.u64 %0, t; }"
        : "=r"(a) : "l"(p));
    return a;
}
__device__ __forceinline__ void cp_async16(uint32_t dst, const void* src) {
    asm volatile("cp.async.cg.shared.global [%0], [%1], 16;" :: "r"(dst), "l"(src));
}
__device__ __forceinline__ void mma16816(float* c, const uint32_t* a, const uint32_t* b) {
    asm volatile(
        "mma.sync.aligned.m16n8k16.row.col.f32.bf16.bf16.f32 "
        "{%0,%1,%2,%3}, {%4,%5,%6,%7}, {%8,%9}, {%0,%1,%2,%3};"
        : "+f"(c[0]), "+f"(c[1]), "+f"(c[2]), "+f"(c[3])
        : "r"(a[0]), "r"(a[1]), "r"(a[2]), "r"(a[3]), "r"(b[0]), "r"(b[1]));
}
__device__ __forceinline__ uint32_t pack_bf2(float f0, float f1) {
    uint32_t u0 = (__bfloat16_as_ushort(__float2bfloat16(f0)));
    uint32_t u1 = (__bfloat16_as_ushort(__float2bfloat16(f1)));
    return u0 | (u1 << 16);
}

// ---------------- GroupNorm statistics --------------------------------------
__global__ void gn_stats(const float* __restrict__ x) {
    int bg = blockIdx.x;
    const float* px = x + (size_t)bg * GN_ELEMS;
    int tid = threadIdx.x;
    float s = 0.f, ss = 0.f;
    for (int i = tid; i < GN_ELEMS; i += 256) {
        float v = px[i];
        s += v; ss += v * v;
    }
    for (int o = 16; o; o >>= 1) {
        s  += __shfl_xor_sync(0xffffffffu, s, o);
        ss += __shfl_xor_sync(0xffffffffu, ss, o);
    }
    __shared__ float sm_s[8], sm_ss[8];
    int lane = tid & 31, warp = tid >> 5;
    if (lane == 0) { sm_s[warp] = s; sm_ss[warp] = ss; }
    __syncthreads();
    if (tid == 0) {
        float ts = 0.f, tss = 0.f;
        for (int i = 0; i < 8; i++) { ts += sm_s[i]; tss += sm_ss[i]; }
        float mean = ts * (1.0f / GN_ELEMS);
        float var  = tss * (1.0f / GN_ELEMS) - mean * mean;
        g_mean[bg] = mean;
        g_rstd[bg] = rsqrtf(var + 1e-6f);
    }
}

// ---------------- GroupNorm apply + transpose + bf16 split -------------------
__global__ void gn_apply(const float* __restrict__ x,
                         const float* __restrict__ w,
                         const float* __restrict__ b,
                         bf16* __restrict__ hh, bf16* __restrict__ hl) {
    __shared__ float tile[32][33];
    int bb = blockIdx.z, c0 = blockIdx.y * 32, n0 = blockIdx.x * 32;
    int tx = threadIdx.x, ty = threadIdx.y;
#pragma unroll
    for (int i = 0; i < 4; i++) {
        int c = c0 + ty + i * 8;
        int n = n0 + tx;
        float v = x[((size_t)bb * CCH + c) * NPIX + n];
        int g = c >> 3;
        v = (v - g_mean[bb * NGRP + g]) * g_rstd[bb * NGRP + g] * w[c] + b[c];
        tile[ty + i * 8][tx] = v;
    }
    __syncthreads();
#pragma unroll
    for (int i = 0; i < 4; i++) {
        int n = n0 + ty + i * 8;
        int c = c0 + tx;
        float v = tile[tx][ty + i * 8];
        size_t idx = ((size_t)bb * NPIX + n) * CCH + c;
        bf16 h = __float2bfloat16(v);
        hh[idx] = h;
        hl[idx] = __float2bfloat16(v - __bfloat162float(h));
    }
}

// ---------------- split 4 weight matrices ------------------------------------
__global__ void split_weights(const float* __restrict__ q, const float* __restrict__ k,
                              const float* __restrict__ v, const float* __restrict__ o,
                              bf16* __restrict__ wh, bf16* __restrict__ wl) {
    int i = blockIdx.x * 256 + threadIdx.x;
    int mat = i >> 16, off = i & 65535;
    const float* src = (mat == 0) ? q : (mat == 1) ? k : (mat == 2) ? v : o;
    float val = src[off];
    bf16 h = __float2bfloat16(val);
    wh[i] = h;
    wl[i] = __float2bfloat16(val - __bfloat162float(h));
}

// ---------------- transpose+split v: [B,N,C] f32 -> [B,C,N] bf16 hi/lo -------
__global__ void v_transpose(const float* __restrict__ v,
                            bf16* __restrict__ th, bf16* __restrict__ tl) {
    __shared__ float tile[32][33];
    int bb = blockIdx.z, c0 = blockIdx.y * 32, n0 = blockIdx.x * 32;
    int tx = threadIdx.x, ty = threadIdx.y;
#pragma unroll
    for (int i = 0; i < 4; i++) {
        int n = n0 + ty + i * 8;
        tile[ty + i * 8][tx] = v[((size_t)bb * NPIX + n) * CCH + c0 + tx];
    }
    __syncthreads();
#pragma unroll
    for (int i = 0; i < 4; i++) {
        int c = c0 + ty + i * 8;
        int n = n0 + tx;
        float val = tile[tx][ty + i * 8];
        size_t idx = ((size_t)bb * CCH + c) * NPIX + n;
        bf16 h = __float2bfloat16(val);
        th[idx] = h;
        tl[idx] = __float2bfloat16(val - __bfloat162float(h));
    }
}

// ---------------- mma.sync GEMM: C = A @ B^T (+bias) -------------------------
// A [M,K] hi/lo bf16 row-major; B [N,K] hi/lo bf16 row-major.
// EMODE 0: fp32 out; EMODE 1: bf16 hi/lo out.
// 128x128x32 tile, 2-stage cp.async pipeline, 8 warps (warp tile 64x32),
// 2 CTAs per SM (80KB smem each).
// Compute (Ah+Al)@(Bh+Bl)^T ~= Ah Bh + Ah Bl + Al Bh  (fp32 accumulate).
#define RS     40                   // padded row stride (elems)
#define TERMSZ (128 * RS)           // 5120 elems = 10240 B
#define STAGESZ (4 * TERMSZ)        // elems per stage
#define SMEMSZ (2 * STAGESZ * 2)    // bytes = 81920

template <int EMODE>
__global__ void __launch_bounds__(256, 2)
mma_gemm(const bf16* __restrict__ Ah, const bf16* __restrict__ Al,
         const bf16* __restrict__ Bh, const bf16* __restrict__ Bl,
         const float* __restrict__ bias,
         float* __restrict__ Cf, bf16* __restrict__ Ch, bf16* __restrict__ Cl,
         int M, int N, int K, long sA, long sB, long sC) {
    extern __shared__ bf16 sm[];
    int tid = threadIdx.x, lane = tid & 31, wid = tid >> 5;
    Ah += (size_t)blockIdx.z * sA;
    Al += (size_t)blockIdx.z * sA;
    Bh += (size_t)blockIdx.z * sB;
    Bl += (size_t)blockIdx.z * sB;
    size_t coff = (size_t)blockIdx.z * sC;
    int tm = blockIdx.y * 128, tn = blockIdx.x * 128;
    int nk = K >> 5;                       // 32-wide K chunks

    int wm0 = (wid & 1) * 64;              // warp m offset in tile
    int wn0 = (wid >> 1) * 32;             // warp n offset in tile
    int gr = lane >> 2, tc = lane & 3;

    uint32_t sb = smem_u32(sm);

    float acc[4][4][4];
#pragma unroll
    for (int i = 0; i < 4; i++)
#pragma unroll
        for (int j = 0; j < 4; j++)
#pragma unroll
            for (int r = 0; r < 4; r++) acc[i][j][r] = 0.f;

    auto load_stage = [&](int chunk) {
        int st = chunk & 1;
        int kb = chunk * 32;
#pragma unroll
        for (int i = 0; i < 8; i++) {
            int c = tid + i * 256;          // 0..2047
            int t = c >> 9;                 // term 0..3
            int idx = c & 511;
            int row = idx >> 2, g = idx & 3;
            const bf16* src = (t == 0) ? Ah : (t == 1) ? Al : (t == 2) ? Bh : Bl;
            int rb = (t < 2) ? tm : tn;
            uint32_t dst = sb + (uint32_t)(st * STAGESZ + t * TERMSZ + row * RS + g * 8) * 2;
            cp_async16(dst, src + ((size_t)(rb + row) * K + kb + g * 8));
        }
        asm volatile("cp.async.commit_group;" ::: "memory");
    };

    load_stage(0);
    if (nk > 1) load_stage(1);

    for (int kt = 0; kt < nk; kt++) {
        if (kt < nk - 1) asm volatile("cp.async.wait_group 1;" ::: "memory");
        else             asm volatile("cp.async.wait_group 0;" ::: "memory");
        __syncthreads();

        const bf16* As_h = sm + (kt & 1) * STAGESZ;
        const bf16* As_l = As_h + TERMSZ;
        const bf16* Bs_h = As_h + 2 * TERMSZ;
        const bf16* Bs_l = As_h + 3 * TERMSZ;

#pragma unroll
        for (int kk = 0; kk < 2; kk++) {
            int k0 = kk * 16 + tc * 2;
            uint32_t bh[4][2], bl[4][2];
#pragma unroll
            for (int ni = 0; ni < 4; ni++) {
                int rn = wn0 + ni * 8 + gr;
                bh[ni][0] = *(const uint32_t*)&Bs_h[rn * RS + k0];
                bh[ni][1] = *(const uint32_t*)&Bs_h[rn * RS + k0 + 8];
                bl[ni][0] = *(const uint32_t*)&Bs_l[rn * RS + k0];
                bl[ni][1] = *(const uint32_t*)&Bs_l[rn * RS + k0 + 8];
            }
#pragma unroll
            for (int mi = 0; mi < 4; mi++) {
                int r = wm0 + mi * 16 + gr;
                uint32_t ah[4], al[4];
                ah[0] = *(const uint32_t*)&As_h[r * RS + k0];
                ah[1] = *(const uint32_t*)&As_h[(r + 8) * RS + k0];
                ah[2] = *(const uint32_t*)&As_h[r * RS + k0 + 8];
                ah[3] = *(const uint32_t*)&As_h[(r + 8) * RS + k0 + 8];
                al[0] = *(const uint32_t*)&As_l[r * RS + k0];
                al[1] = *(const uint32_t*)&As_l[(r + 8) * RS + k0];
                al[2] = *(const uint32_t*)&As_l[r * RS + k0 + 8];
                al[3] = *(const uint32_t*)&As_l[(r + 8) * RS + k0 + 8];
#pragma unroll
                for (int ni = 0; ni < 4; ni++) {
                    mma16816(acc[mi][ni], ah, bh[ni]);
                    mma16816(acc[mi][ni], ah, bl[ni]);
                    mma16816(acc[mi][ni], al, bh[ni]);
                }
            }
        }
        __syncthreads();
        if (kt + 2 < nk) load_stage(kt + 2);
    }

    // epilogue
#pragma unroll
    for (int mi = 0; mi < 4; mi++) {
#pragma unroll
        for (int ni = 0; ni < 4; ni++) {
            int m = tm + wm0 + mi * 16 + gr;
            int n = tn + wn0 + ni * 8 + tc * 2;
            float b0v = bias ? bias[n]     : 0.f;
            float b1v = bias ? bias[n + 1] : 0.f;
            float c0 = acc[mi][ni][0] + b0v, c1 = acc[mi][ni][1] + b1v;
            float c2 = acc[mi][ni][2] + b0v, c3 = acc[mi][ni][3] + b1v;
            if (EMODE == 0) {
                float2 v0 = {c0, c1}, v1 = {c2, c3};
                *(float2*)&Cf[coff + (size_t)m * N + n]       = v0;
                *(float2*)&Cf[coff + (size_t)(m + 8) * N + n] = v1;
            } else {
                bf16 h0 = __float2bfloat16(c0), h1 = __float2bfloat16(c1);
                bf16 h2 = __float2bfloat16(c2), h3 = __float2bfloat16(c3);
                uint32_t hi0 = (uint32_t)__bfloat16_as_ushort(h0) |
                               ((uint32_t)__bfloat16_as_ushort(h1) << 16);
                uint32_t hi1 = (uint32_t)__bfloat16_as_ushort(h2) |
                               ((uint32_t)__bfloat16_as_ushort(h3) << 16);
                uint32_t lo0 = pack_bf2(c0 - __bfloat162float(h0), c1 - __bfloat162float(h1));
                uint32_t lo1 = pack_bf2(c2 - __bfloat162float(h2), c3 - __bfloat162float(h3));
                *(uint32_t*)&Ch[coff + (size_t)m * N + n]       = hi0;
                *(uint32_t*)&Ch[coff + (size_t)(m + 8) * N + n] = hi1;
                *(uint32_t*)&Cl[coff + (size_t)m * N + n]       = lo0;
                *(uint32_t*)&Cl[coff + (size_t)(m + 8) * N + n] = lo1;
            }
        }
    }
}

// ---------------- row softmax -> bf16 hi/lo probs ----------------------------
__global__ void softmax_rows(const float* __restrict__ S,
                             bf16* __restrict__ Ph, bf16* __restrict__ Pl) {
    size_t row = blockIdx.x;
    const float* p = S + row * (size_t)NPIX;
    int tid = threadIdx.x;
    float vals[16];
    float mx = -CUDART_INF_F;
#pragma unroll
    for (int i = 0; i < 16; i++) {
        vals[i] = p[tid + i * 256];
        mx = fmaxf(mx, vals[i]);
    }
    __shared__ float sm[8];
    for (int o = 16; o; o >>= 1) mx = fmaxf(mx, __shfl_xor_sync(0xffffffffu, mx, o));
    int lane = tid & 31, warp = tid >> 5;
    if (lane == 0) sm[warp] = mx;
    __syncthreads();
    if (warp == 0) {
        float v = sm[lane & 7];
        for (int o = 4; o; o >>= 1) v = fmaxf(v, __shfl_xor_sync(0xffffffffu, v, o));
        if (lane == 0) sm[0] = v;
    }
    __syncthreads();
    mx = sm[0];
    __syncthreads();

    float sum = 0.f;
#pragma unroll
    for (int i = 0; i < 16; i++) {
        vals[i] = __expf((vals[i] - mx) * SCALE);
        sum += vals[i];
    }
    for (int o = 16; o; o >>= 1) sum += __shfl_xor_sync(0xffffffffu, sum, o);
    if (lane == 0) sm[warp] = sum;
    __syncthreads();
    if (warp == 0) {
        float v = sm[lane & 7];
        for (int o = 4; o; o >>= 1) v += __shfl_xor_sync(0xffffffffu, v, o);
        if (lane == 0) sm[0] = v;
    }
    __syncthreads();
    float inv = 1.0f / sm[0];
    size_t obase = row * (size_t)NPIX;
#pragma unroll
    for (int i = 0; i < 16; i++) {
        float pv = vals[i] * inv;
        bf16 h = __float2bfloat16(pv);
        size_t o = obase + tid + i * 256;
        Ph[o] = h;
        Pl[o] = __float2bfloat16(pv - __bfloat162float(h));
    }
}

// ---------------- final: y = (x + tmp^T) * 1/sqrt(2) -------------------------
__global__ void final_residual(const float* __restrict__ x,
                               const float* __restrict__ tmp,
                               float* __restrict__ y) {
    __shared__ float tile[32][33];
    int bb = blockIdx.z, c0 = blockIdx.y * 32, n0 = blockIdx.x * 32;
    int tx = threadIdx.x, ty = threadIdx.y;
#pragma unroll
    for (int i = 0; i < 4; i++) {
        int n = n0 + ty + i * 8;
        tile[ty + i * 8][tx] = tmp[((size_t)bb * NPIX + n) * CCH + c0 + tx];
    }
    __syncthreads();
#pragma unroll
    for (int i = 0; i < 4; i++) {
        int c = c0 + ty + i * 8;
        int n = n0 + tx;
        size_t idx = ((size_t)bb * CCH + c) * NPIX + n;
        y[idx] = (x[idx] + tile[tx][ty + i * 8]) * INV_SQRT2;
    }
}

// ---------------- launch ------------------------------------------------------
extern "C" void kernel_launch(void* const* d_in, const int* in_sizes, int n_in,
                              void* d_out, int out_size) {
    const float* x  = (const float*)d_in[0];
    const float* gw = (const float*)d_in[1];
    const float* gb = (const float*)d_in[2];
    const float* Wq = (const float*)d_in[3];
    const float* bq = (const float*)d_in[4];
    const float* Wk = (const float*)d_in[5];
    const float* bk = (const float*)d_in[6];
    const float* Wv = (const float*)d_in[7];
    const float* bv = (const float*)d_in[8];
    const float* Wo = (const float*)d_in[9];
    const float* bo = (const float*)d_in[10];
    float* y = (float*)d_out;

    cudaFuncSetAttribute(mma_gemm<0>, cudaFuncAttributeMaxDynamicSharedMemorySize, SMEMSZ);
    cudaFuncSetAttribute(mma_gemm<1>, cudaFuncAttributeMaxDynamicSharedMemorySize, SMEMSZ);

    bf16 *hs_h, *hs_l, *q_h, *q_l, *k_h, *k_l, *vt_h, *vt_l, *p_h, *p_l, *ao_h, *ao_l, *w_h, *w_l;
    float *v, *s, *tmp;
    cudaGetSymbolAddress((void**)&hs_h, g_hs_h);
    cudaGetSymbolAddress((void**)&hs_l, g_hs_l);
    cudaGetSymbolAddress((void**)&q_h,  g_q_h);
    cudaGetSymbolAddress((void**)&q_l,  g_q_l);
    cudaGetSymbolAddress((void**)&k_h,  g_k_h);
    cudaGetSymbolAddress((void**)&k_l,  g_k_l);
    cudaGetSymbolAddress((void**)&v,    g_v);
    cudaGetSymbolAddress((void**)&vt_h, g_vt_h);
    cudaGetSymbolAddress((void**)&vt_l, g_vt_l);
    cudaGetSymbolAddress((void**)&s,    g_s);
    cudaGetSymbolAddress((void**)&p_h,  g_p_h);
    cudaGetSymbolAddress((void**)&p_l,  g_p_l);
    cudaGetSymbolAddress((void**)&ao_h, g_ao_h);
    cudaGetSymbolAddress((void**)&ao_l, g_ao_l);
    cudaGetSymbolAddress((void**)&tmp,  g_tmp);
    cudaGetSymbolAddress((void**)&w_h,  g_w_h);
    cudaGetSymbolAddress((void**)&w_l,  g_w_l);

    const long NC = (long)NPIX * CCH;
    const long NN = (long)NPIX * NPIX;
    const int  MALL = BATCH * NPIX;   // 16384

    gn_stats<<<BATCH * NGRP, 256>>>(x);
    gn_apply<<<dim3(NPIX / 32, CCH / 32, BATCH), dim3(32, 8)>>>(x, gw, gb, hs_h, hs_l);
    split_weights<<<1024, 256>>>(Wq, Wk, Wv, Wo, w_h, w_l);

    // QKV projections: [16384,256] @ W^T + b
    mma_gemm<1><<<dim3(2, MALL / 128, 1), 256, SMEMSZ>>>(
        hs_h, hs_l, w_h, w_l, bq, nullptr, q_h, q_l, MALL, CCH, CCH, 0, 0, 0);
    mma_gemm<1><<<dim3(2, MALL / 128, 1), 256, SMEMSZ>>>(
        hs_h, hs_l, w_h + 65536, w_l + 65536, bk, nullptr, k_h, k_l, MALL, CCH, CCH, 0, 0, 0);
    mma_gemm<0><<<dim3(2, MALL / 128, 1), 256, SMEMSZ>>>(
        hs_h, hs_l, w_h + 131072, w_l + 131072, bv, v, nullptr, nullptr, MALL, CCH, CCH, 0, 0, 0);
    v_transpose<<<dim3(NPIX / 32, CCH / 32, BATCH), dim3(32, 8)>>>(v, vt_h, vt_l);

    // S = Q @ K^T (batched over 4)
    mma_gemm<0><<<dim3(32, 32, BATCH), 256, SMEMSZ>>>(
        q_h, q_l, k_h, k_l, nullptr, s, nullptr, nullptr, NPIX, NPIX, CCH, NC, NC, NN);

    softmax_rows<<<MALL, 256>>>(s, p_h, p_l);

    // AO = P @ V  (B operand = V^T as [C,N] K-major)
    mma_gemm<1><<<dim3(2, 32, BATCH), 256, SMEMSZ>>>(
        p_h, p_l, vt_h, vt_l, nullptr, nullptr, ao_h, ao_l, NPIX, CCH, NPIX, NN, NC, NC);

    // O projection
    mma_gemm<0><<<dim3(2, MALL / 128, 1), 256, SMEMSZ>>>(
        ao_h, ao_l, w_h + 196608, w_l + 196608, bo, tmp, nullptr, nullptr, MALL, CCH, CCH, 0, 0, 0);

    final_residual<<<dim3(NPIX / 32, CCH / 32, BATCH), dim3(32, 8)>>>(x, tmp, y);
}

// round 5
// speedup vs baseline: 2.3248x; 1.0920x over previous
#include <cuda_runtime.h>
#include <cuda_bf16.h>
#include <math_constants.h>
#include <cstdint>

typedef __nv_bfloat16 bf16;

#define BATCH 4
#define CCH   256
#define NPIX  4096
#define NGRP  32
#define GN_ELEMS (8 * NPIX)
#define SCALE 0.0625f
#define INV_SQRT2 0.70710678118654752f

#define NELT (BATCH * NPIX * CCH)            // 4,194,304
#define NNELT ((size_t)BATCH * NPIX * NPIX)  // 67,108,864

// ---------------- scratch (device globals) ---------------------------------
__device__ bf16  g_hs_h[NELT], g_hs_l[NELT];
__device__ bf16  g_q_h [NELT], g_q_l [NELT];
__device__ bf16  g_k_h [NELT], g_k_l [NELT];
__device__ float g_v   [NELT];
__device__ bf16  g_vt_h[NELT], g_vt_l[NELT];
__device__ float g_s   [NNELT];
__device__ bf16  g_p_h [NNELT], g_p_l[NNELT];
__device__ bf16  g_ao_h[NELT], g_ao_l[NELT];
__device__ float g_tmp [NELT];
__device__ bf16  g_w_h [4 * CCH * CCH], g_w_l[4 * CCH * CCH];
__device__ float g_mean[BATCH * NGRP], g_rstd[BATCH * NGRP];

// ---------------- helpers ----------------------------------------------------
__device__ __forceinline__ uint32_t smem_u32(const void* p) {
    uint32_t a;
    asm("{ .reg .u64 t; cvta.to.shared.u64 t, %1; cvt.u32.u64 %0, t; }"
        : "=r"(a) : "l"(p));
    return a;
}
__device__ __forceinline__ void cp_async16(uint32_t dst, const void* src) {
    asm volatile("cp.async.cg.shared.global [%0], [%1], 16;" :: "r"(dst), "l"(src));
}
__device__ __forceinline__ void ldsm_x4(uint32_t addr, uint32_t* r) {
    asm volatile("ldmatrix.sync.aligned.m8n8.x4.shared.b16 {%0,%1,%2,%3}, [%4];"
                 : "=r"(r[0]), "=r"(r[1]), "=r"(r[2]), "=r"(r[3]) : "r"(addr));
}
__device__ __forceinline__ void mma16816(float* c, const uint32_t* a, const uint32_t* b) {
    asm volatile(
        "mma.sync.aligned.m16n8k16.row.col.f32.bf16.bf16.f32 "
        "{%0,%1,%2,%3}, {%4,%5,%6,%7}, {%8,%9}, {%0,%1,%2,%3};"
        : "+f"(c[0]), "+f"(c[1]), "+f"(c[2]), "+f"(c[3])
        : "r"(a[0]), "r"(a[1]), "r"(a[2]), "r"(a[3]), "r"(b[0]), "r"(b[1]));
}
__device__ __forceinline__ uint32_t pack_bf2(float f0, float f1) {
    uint32_t u0 = (__bfloat16_as_ushort(__float2bfloat16(f0)));
    uint32_t u1 = (__bfloat16_as_ushort(__float2bfloat16(f1)));
    return u0 | (u1 << 16);
}

// ---------------- GroupNorm statistics --------------------------------------
__global__ void gn_stats(const float* __restrict__ x) {
    int bg = blockIdx.x;
    const float* px = x + (size_t)bg * GN_ELEMS;
    int tid = threadIdx.x;
    float s = 0.f, ss = 0.f;
    for (int i = tid; i < GN_ELEMS; i += 256) {
        float v = px[i];
        s += v; ss += v * v;
    }
    for (int o = 16; o; o >>= 1) {
        s  += __shfl_xor_sync(0xffffffffu, s, o);
        ss += __shfl_xor_sync(0xffffffffu, ss, o);
    }
    __shared__ float sm_s[8], sm_ss[8];
    int lane = tid & 31, warp = tid >> 5;
    if (lane == 0) { sm_s[warp] = s; sm_ss[warp] = ss; }
    __syncthreads();
    if (tid == 0) {
        float ts = 0.f, tss = 0.f;
        for (int i = 0; i < 8; i++) { ts += sm_s[i]; tss += sm_ss[i]; }
        float mean = ts * (1.0f / GN_ELEMS);
        float var  = tss * (1.0f / GN_ELEMS) - mean * mean;
        g_mean[bg] = mean;
        g_rstd[bg] = rsqrtf(var + 1e-6f);
    }
}

// ---------------- GroupNorm apply + transpose + bf16 split -------------------
__global__ void gn_apply(const float* __restrict__ x,
                         const float* __restrict__ w,
                         const float* __restrict__ b,
                         bf16* __restrict__ hh, bf16* __restrict__ hl) {
    __shared__ float tile[32][33];
    int bb = blockIdx.z, c0 = blockIdx.y * 32, n0 = blockIdx.x * 32;
    int tx = threadIdx.x, ty = threadIdx.y;
#pragma unroll
    for (int i = 0; i < 4; i++) {
        int c = c0 + ty + i * 8;
        int n = n0 + tx;
        float v = x[((size_t)bb * CCH + c) * NPIX + n];
        int g = c >> 3;
        v = (v - g_mean[bb * NGRP + g]) * g_rstd[bb * NGRP + g] * w[c] + b[c];
        tile[ty + i * 8][tx] = v;
    }
    __syncthreads();
#pragma unroll
    for (int i = 0; i < 4; i++) {
        int n = n0 + ty + i * 8;
        int c = c0 + tx;
        float v = tile[tx][ty + i * 8];
        size_t idx = ((size_t)bb * NPIX + n) * CCH + c;
        bf16 h = __float2bfloat16(v);
        hh[idx] = h;
        hl[idx] = __float2bfloat16(v - __bfloat162float(h));
    }
}

// ---------------- split 4 weight matrices ------------------------------------
__global__ void split_weights(const float* __restrict__ q, const float* __restrict__ k,
                              const float* __restrict__ v, const float* __restrict__ o,
                              bf16* __restrict__ wh, bf16* __restrict__ wl) {
    int i = blockIdx.x * 256 + threadIdx.x;
    int mat = i >> 16, off = i & 65535;
    const float* src = (mat == 0) ? q : (mat == 1) ? k : (mat == 2) ? v : o;
    float val = src[off];
    bf16 h = __float2bfloat16(val);
    wh[i] = h;
    wl[i] = __float2bfloat16(val - __bfloat162float(h));
}

// ---------------- transpose+split v: [B,N,C] f32 -> [B,C,N] bf16 hi/lo -------
__global__ void v_transpose(const float* __restrict__ v,
                            bf16* __restrict__ th, bf16* __restrict__ tl) {
    __shared__ float tile[32][33];
    int bb = blockIdx.z, c0 = blockIdx.y * 32, n0 = blockIdx.x * 32;
    int tx = threadIdx.x, ty = threadIdx.y;
#pragma unroll
    for (int i = 0; i < 4; i++) {
        int n = n0 + ty + i * 8;
        tile[ty + i * 8][tx] = v[((size_t)bb * NPIX + n) * CCH + c0 + tx];
    }
    __syncthreads();
#pragma unroll
    for (int i = 0; i < 4; i++) {
        int c = c0 + ty + i * 8;
        int n = n0 + tx;
        float val = tile[tx][ty + i * 8];
        size_t idx = ((size_t)bb * CCH + c) * NPIX + n;
        bf16 h = __float2bfloat16(val);
        th[idx] = h;
        tl[idx] = __float2bfloat16(val - __bfloat162float(h));
    }
}

// ---------------- mma.sync GEMM: C = A @ B^T (+bias) -------------------------
// A [M,K] hi/lo bf16 row-major; B [N,K] hi/lo bf16 row-major.
// EMODE 0: fp32 out; EMODE 1: bf16 hi/lo out.
// 128x128x32 tile, 2-stage cp.async pipeline, 8 warps (warp tile 64x32),
// 2 CTAs per SM. Fragments via ldmatrix.x4 (conflict-free on 80B row stride).
// Compute (Ah+Al)@(Bh+Bl)^T ~= Ah Bh + Ah Bl + Al Bh  (fp32 accumulate).
#define RS     40                   // padded row stride (elems)
#define TERMSZ (128 * RS)           // 5120 elems = 10240 B
#define STAGESZ (4 * TERMSZ)        // elems per stage
#define SMEMSZ (2 * STAGESZ * 2)    // bytes = 81920

template <int EMODE>
__global__ void __launch_bounds__(256, 2)
mma_gemm(const bf16* __restrict__ Ah, const bf16* __restrict__ Al,
         const bf16* __restrict__ Bh, const bf16* __restrict__ Bl,
         const float* __restrict__ bias,
         float* __restrict__ Cf, bf16* __restrict__ Ch, bf16* __restrict__ Cl,
         int M, int N, int K, long sA, long sB, long sC) {
    extern __shared__ bf16 sm[];
    int tid = threadIdx.x, lane = tid & 31, wid = tid >> 5;
    Ah += (size_t)blockIdx.z * sA;
    Al += (size_t)blockIdx.z * sA;
    Bh += (size_t)blockIdx.z * sB;
    Bl += (size_t)blockIdx.z * sB;
    size_t coff = (size_t)blockIdx.z * sC;
    int tm = blockIdx.y * 128, tn = blockIdx.x * 128;
    int nk = K >> 5;                       // 32-wide K chunks

    int wm0 = (wid & 1) * 64;              // warp m offset in tile
    int wn0 = (wid >> 1) * 32;             // warp n offset in tile
    int gr = lane >> 2, tc = lane & 3;

    // ldmatrix per-lane row addressing (matrix id = lane>>3)
    int lr = lane & 7, lm = lane >> 3;
    uint32_t rowA = (uint32_t)(wm0 + (lm & 1) * 8 + lr);
    uint32_t kAoff = (uint32_t)((lm >> 1) * 8);
    uint32_t rowB = (uint32_t)(wn0 + (lm >> 1) * 8 + lr);
    uint32_t kBoff = (uint32_t)((lm & 1) * 8);

    uint32_t sb = smem_u32(sm);

    float acc[4][4][4];
#pragma unroll
    for (int i = 0; i < 4; i++)
#pragma unroll
        for (int j = 0; j < 4; j++)
#pragma unroll
            for (int r = 0; r < 4; r++) acc[i][j][r] = 0.f;

    auto load_stage = [&](int chunk) {
        int st = chunk & 1;
        int kb = chunk * 32;
#pragma unroll
        for (int i = 0; i < 8; i++) {
            int c = tid + i * 256;          // 0..2047
            int t = c >> 9;                 // term 0..3
            int idx = c & 511;
            int row = idx >> 2, g = idx & 3;
            const bf16* src = (t == 0) ? Ah : (t == 1) ? Al : (t == 2) ? Bh : Bl;
            int rb = (t < 2) ? tm : tn;
            uint32_t dst = sb + (uint32_t)(st * STAGESZ + t * TERMSZ + row * RS + g * 8) * 2;
            cp_async16(dst, src + ((size_t)(rb + row) * K + kb + g * 8));
        }
        asm volatile("cp.async.commit_group;" ::: "memory");
    };

    load_stage(0);
    if (nk > 1) load_stage(1);

    for (int kt = 0; kt < nk; kt++) {
        if (kt < nk - 1) asm volatile("cp.async.wait_group 1;" ::: "memory");
        else             asm volatile("cp.async.wait_group 0;" ::: "memory");
        __syncthreads();

        uint32_t stage = sb + (uint32_t)((kt & 1) * STAGESZ) * 2;
        uint32_t sAh = stage;
        uint32_t sAl = stage + TERMSZ * 2;
        uint32_t sBh = stage + 2 * TERMSZ * 2;
        uint32_t sBl = stage + 3 * TERMSZ * 2;

#pragma unroll
        for (int kk = 0; kk < 2; kk++) {
            uint32_t k0 = (uint32_t)(kk * 16);
            // B fragments: ldmatrix.x4 per ni-pair per term
            uint32_t bh[4][2], bl[4][2];
#pragma unroll
            for (int p = 0; p < 2; p++) {
                uint32_t boff = ((rowB + p * 16) * RS + k0 + kBoff) * 2;
                ldsm_x4(sBh + boff, &bh[p * 2][0]);
                ldsm_x4(sBl + boff, &bl[p * 2][0]);
            }
#pragma unroll
            for (int mi = 0; mi < 4; mi++) {
                uint32_t aoff = ((rowA + mi * 16) * RS + k0 + kAoff) * 2;
                uint32_t ah[4], al[4];
                ldsm_x4(sAh + aoff, ah);
                ldsm_x4(sAl + aoff, al);
#pragma unroll
                for (int ni = 0; ni < 4; ni++) {
                    mma16816(acc[mi][ni], ah, bh[ni]);
                    mma16816(acc[mi][ni], ah, bl[ni]);
                    mma16816(acc[mi][ni], al, bh[ni]);
                }
            }
        }
        __syncthreads();
        if (kt + 2 < nk) load_stage(kt + 2);
    }

    // epilogue
#pragma unroll
    for (int mi = 0; mi < 4; mi++) {
#pragma unroll
        for (int ni = 0; ni < 4; ni++) {
            int m = tm + wm0 + mi * 16 + gr;
            int n = tn + wn0 + ni * 8 + tc * 2;
            float b0v = bias ? bias[n]     : 0.f;
            float b1v = bias ? bias[n + 1] : 0.f;
            float c0 = acc[mi][ni][0] + b0v, c1 = acc[mi][ni][1] + b1v;
            float c2 = acc[mi][ni][2] + b0v, c3 = acc[mi][ni][3] + b1v;
            if (EMODE == 0) {
                float2 v0 = {c0, c1}, v1 = {c2, c3};
                *(float2*)&Cf[coff + (size_t)m * N + n]       = v0;
                *(float2*)&Cf[coff + (size_t)(m + 8) * N + n] = v1;
            } else {
                bf16 h0 = __float2bfloat16(c0), h1 = __float2bfloat16(c1);
                bf16 h2 = __float2bfloat16(c2), h3 = __float2bfloat16(c3);
                uint32_t hi0 = (uint32_t)__bfloat16_as_ushort(h0) |
                               ((uint32_t)__bfloat16_as_ushort(h1) << 16);
                uint32_t hi1 = (uint32_t)__bfloat16_as_ushort(h2) |
                               ((uint32_t)__bfloat16_as_ushort(h3) << 16);
                uint32_t lo0 = pack_bf2(c0 - __bfloat162float(h0), c1 - __bfloat162float(h1));
                uint32_t lo1 = pack_bf2(c2 - __bfloat162float(h2), c3 - __bfloat162float(h3));
                *(uint32_t*)&Ch[coff + (size_t)m * N + n]       = hi0;
                *(uint32_t*)&Ch[coff + (size_t)(m + 8) * N + n] = hi1;
                *(uint32_t*)&Cl[coff + (size_t)m * N + n]       = lo0;
                *(uint32_t*)&Cl[coff + (size_t)(m + 8) * N + n] = lo1;
            }
        }
    }
}

// ---------------- row softmax -> bf16 hi/lo probs ----------------------------
__global__ void softmax_rows(const float* __restrict__ S,
                             bf16* __restrict__ Ph, bf16* __restrict__ Pl) {
    size_t row = blockIdx.x;
    const float* p = S + row * (size_t)NPIX;
    int tid = threadIdx.x;
    float vals[16];
    float mx = -CUDART_INF_F;
#pragma unroll
    for (int i = 0; i < 16; i++) {
        vals[i] = p[tid + i * 256];
        mx = fmaxf(mx, vals[i]);
    }
    __shared__ float sm[8];
    for (int o = 16; o; o >>= 1) mx = fmaxf(mx, __shfl_xor_sync(0xffffffffu, mx, o));
    int lane = tid & 31, warp = tid >> 5;
    if (lane == 0) sm[warp] = mx;
    __syncthreads();
    if (warp == 0) {
        float v = sm[lane & 7];
        for (int o = 4; o; o >>= 1) v = fmaxf(v, __shfl_xor_sync(0xffffffffu, v, o));
        if (lane == 0) sm[0] = v;
    }
    __syncthreads();
    mx = sm[0];
    __syncthreads();

    float sum = 0.f;
#pragma unroll
    for (int i = 0; i < 16; i++) {
        vals[i] = __expf((vals[i] - mx) * SCALE);
        sum += vals[i];
    }
    for (int o = 16; o; o >>= 1) sum += __shfl_xor_sync(0xffffffffu, sum, o);
    if (lane == 0) sm[warp] = sum;
    __syncthreads();
    if (warp == 0) {
        float v = sm[lane & 7];
        for (int o = 4; o; o >>= 1) v += __shfl_xor_sync(0xffffffffu, v, o);
        if (lane == 0) sm[0] = v;
    }
    __syncthreads();
    float inv = 1.0f / sm[0];
    size_t obase = row * (size_t)NPIX;
#pragma unroll
    for (int i = 0; i < 16; i++) {
        float pv = vals[i] * inv;
        bf16 h = __float2bfloat16(pv);
        size_t o = obase + tid + i * 256;
        Ph[o] = h;
        Pl[o] = __float2bfloat16(pv - __bfloat162float(h));
    }
}

// ---------------- final: y = (x + tmp^T) * 1/sqrt(2) -------------------------
__global__ void final_residual(const float* __restrict__ x,
                               const float* __restrict__ tmp,
                               float* __restrict__ y) {
    __shared__ float tile[32][33];
    int bb = blockIdx.z, c0 = blockIdx.y * 32, n0 = blockIdx.x * 32;
    int tx = threadIdx.x, ty = threadIdx.y;
#pragma unroll
    for (int i = 0; i < 4; i++) {
        int n = n0 + ty + i * 8;
        tile[ty + i * 8][tx] = tmp[((size_t)bb * NPIX + n) * CCH + c0 + tx];
    }
    __syncthreads();
#pragma unroll
    for (int i = 0; i < 4; i++) {
        int c = c0 + ty + i * 8;
        int n = n0 + tx;
        size_t idx = ((size_t)bb * CCH + c) * NPIX + n;
        y[idx] = (x[idx] + tile[tx][ty + i * 8]) * INV_SQRT2;
    }
}

// ---------------- launch ------------------------------------------------------
extern "C" void kernel_launch(void* const* d_in, const int* in_sizes, int n_in,
                              void* d_out, int out_size) {
    const float* x  = (const float*)d_in[0];
    const float* gw = (const float*)d_in[1];
    const float* gb = (const float*)d_in[2];
    const float* Wq = (const float*)d_in[3];
    const float* bq = (const float*)d_in[4];
    const float* Wk = (const float*)d_in[5];
    const float* bk = (const float*)d_in[6];
    const float* Wv = (const float*)d_in[7];
    const float* bv = (const float*)d_in[8];
    const float* Wo = (const float*)d_in[9];
    const float* bo = (const float*)d_in[10];
    float* y = (float*)d_out;

    cudaFuncSetAttribute(mma_gemm<0>, cudaFuncAttributeMaxDynamicSharedMemorySize, SMEMSZ);
    cudaFuncSetAttribute(mma_gemm<1>, cudaFuncAttributeMaxDynamicSharedMemorySize, SMEMSZ);

    bf16 *hs_h, *hs_l, *q_h, *q_l, *k_h, *k_l, *vt_h, *vt_l, *p_h, *p_l, *ao_h, *ao_l, *w_h, *w_l;
    float *v, *s, *tmp;
    cudaGetSymbolAddress((void**)&hs_h, g_hs_h);
    cudaGetSymbolAddress((void**)&hs_l, g_hs_l);
    cudaGetSymbolAddress((void**)&q_h,  g_q_h);
    cudaGetSymbolAddress((void**)&q_l,  g_q_l);
    cudaGetSymbolAddress((void**)&k_h,  g_k_h);
    cudaGetSymbolAddress((void**)&k_l,  g_k_l);
    cudaGetSymbolAddress((void**)&v,    g_v);
    cudaGetSymbolAddress((void**)&vt_h, g_vt_h);
    cudaGetSymbolAddress((void**)&vt_l, g_vt_l);
    cudaGetSymbolAddress((void**)&s,    g_s);
    cudaGetSymbolAddress((void**)&p_h,  g_p_h);
    cudaGetSymbolAddress((void**)&p_l,  g_p_l);
    cudaGetSymbolAddress((void**)&ao_h, g_ao_h);
    cudaGetSymbolAddress((void**)&ao_l, g_ao_l);
    cudaGetSymbolAddress((void**)&tmp,  g_tmp);
    cudaGetSymbolAddress((void**)&w_h,  g_w_h);
    cudaGetSymbolAddress((void**)&w_l,  g_w_l);

    const long NC = (long)NPIX * CCH;
    const long NN = (long)NPIX * NPIX;
    const int  MALL = BATCH * NPIX;   // 16384

    gn_stats<<<BATCH * NGRP, 256>>>(x);
    gn_apply<<<dim3(NPIX / 32, CCH / 32, BATCH), dim3(32, 8)>>>(x, gw, gb, hs_h, hs_l);
    split_weights<<<1024, 256>>>(Wq, Wk, Wv, Wo, w_h, w_l);

    // QKV projections: [16384,256] @ W^T + b
    mma_gemm<1><<<dim3(2, MALL / 128, 1), 256, SMEMSZ>>>(
        hs_h, hs_l, w_h, w_l, bq, nullptr, q_h, q_l, MALL, CCH, CCH, 0, 0, 0);
    mma_gemm<1><<<dim3(2, MALL / 128, 1), 256, SMEMSZ>>>(
        hs_h, hs_l, w_h + 65536, w_l + 65536, bk, nullptr, k_h, k_l, MALL, CCH, CCH, 0, 0, 0);
    mma_gemm<0><<<dim3(2, MALL / 128, 1), 256, SMEMSZ>>>(
        hs_h, hs_l, w_h + 131072, w_l + 131072, bv, v, nullptr, nullptr, MALL, CCH, CCH, 0, 0, 0);
    v_transpose<<<dim3(NPIX / 32, CCH / 32, BATCH), dim3(32, 8)>>>(v, vt_h, vt_l);

    // S = Q @ K^T (batched over 4)
    mma_gemm<0><<<dim3(32, 32, BATCH), 256, SMEMSZ>>>(
        q_h, q_l, k_h, k_l, nullptr, s, nullptr, nullptr, NPIX, NPIX, CCH, NC, NC, NN);

    softmax_rows<<<MALL, 256>>>(s, p_h, p_l);

    // AO = P @ V  (B operand = V^T as [C,N] K-major)
    mma_gemm<1><<<dim3(2, 32, BATCH), 256, SMEMSZ>>>(
        p_h, p_l, vt_h, vt_l, nullptr, nullptr, ao_h, ao_l, NPIX, CCH, NPIX, NN, NC, NC);

    // O projection
    mma_gemm<0><<<dim3(2, MALL / 128, 1), 256, SMEMSZ>>>(
        ao_h, ao_l, w_h + 196608, w_l + 196608, bo, tmp, nullptr, nullptr, MALL, CCH, CCH, 0, 0, 0);

    final_residual<<<dim3(NPIX / 32, CCH / 32, BATCH), dim3(32, 8)>>>(x, tmp, y);
}

// round 6
// speedup vs baseline: 2.3536x; 1.0124x over previous
#include <cuda_runtime.h>
#include <cuda_bf16.h>
#include <math_constants.h>
#include <cstdint>

typedef __nv_bfloat16 bf16;

#define BATCH 4
#define CCH   256
#define NPIX  4096
#define NGRP  32
#define GN_ELEMS (8 * NPIX)
#define SCALE 0.0625f
#define INV_SQRT2 0.70710678118654752f

#define NELT (BATCH * NPIX * CCH)            // 4,194,304
#define NNELT ((size_t)BATCH * NPIX * NPIX)  // 67,108,864

// ---------------- scratch (device globals) ---------------------------------
__device__ bf16  g_hs_h[NELT], g_hs_l[NELT];
__device__ bf16  g_q_h [NELT], g_q_l [NELT];
__device__ bf16  g_k_h [NELT], g_k_l [NELT];
__device__ float g_v   [NELT];
__device__ bf16  g_vt_h[NELT], g_vt_l[NELT];
__device__ bf16  g_p_h [NNELT], g_p_l[NNELT];   // unnormalized exp(S*scale)
__device__ bf16  g_ao_h[NELT], g_ao_l[NELT];
__device__ float g_tmp [NELT];
__device__ bf16  g_w_h [4 * CCH * CCH], g_w_l[4 * CCH * CCH];
__device__ float g_mean[BATCH * NGRP], g_rstd[BATCH * NGRP];
__device__ float g_rowsum[BATCH * NPIX];        // softmax denominators

// ---------------- helpers ----------------------------------------------------
__device__ __forceinline__ uint32_t smem_u32(const void* p) {
    uint32_t a;
    asm("{ .reg .u64 t; cvta.to.shared.u64 t, %1; cvt.u32.u64 %0, t; }"
        : "=r"(a) : "l"(p));
    return a;
}
__device__ __forceinline__ void cp_async16(uint32_t dst, const void* src) {
    asm volatile("cp.async.cg.shared.global [%0], [%1], 16;" :: "r"(dst), "l"(src));
}
__device__ __forceinline__ void ldsm_x4(uint32_t addr, uint32_t* r) {
    asm volatile("ldmatrix.sync.aligned.m8n8.x4.shared.b16 {%0,%1,%2,%3}, [%4];"
                 : "=r"(r[0]), "=r"(r[1]), "=r"(r[2]), "=r"(r[3]) : "r"(addr));
}
__device__ __forceinline__ void mma16816(float* c, const uint32_t* a, const uint32_t* b) {
    asm volatile(
        "mma.sync.aligned.m16n8k16.row.col.f32.bf16.bf16.f32 "
        "{%0,%1,%2,%3}, {%4,%5,%6,%7}, {%8,%9}, {%0,%1,%2,%3};"
        : "+f"(c[0]), "+f"(c[1]), "+f"(c[2]), "+f"(c[3])
        : "r"(a[0]), "r"(a[1]), "r"(a[2]), "r"(a[3]), "r"(b[0]), "r"(b[1]));
}
__device__ __forceinline__ uint32_t pack_bf2(float f0, float f1) {
    uint32_t u0 = (__bfloat16_as_ushort(__float2bfloat16(f0)));
    uint32_t u1 = (__bfloat16_as_ushort(__float2bfloat16(f1)));
    return u0 | (u1 << 16);
}

// ---------------- GroupNorm statistics --------------------------------------
__global__ void gn_stats(const float* __restrict__ x) {
    int bg = blockIdx.x;
    const float* px = x + (size_t)bg * GN_ELEMS;
    int tid = threadIdx.x;
    float s = 0.f, ss = 0.f;
    for (int i = tid; i < GN_ELEMS; i += 256) {
        float v = px[i];
        s += v; ss += v * v;
    }
    for (int o = 16; o; o >>= 1) {
        s  += __shfl_xor_sync(0xffffffffu, s, o);
        ss += __shfl_xor_sync(0xffffffffu, ss, o);
    }
    __shared__ float sm_s[8], sm_ss[8];
    int lane = tid & 31, warp = tid >> 5;
    if (lane == 0) { sm_s[warp] = s; sm_ss[warp] = ss; }
    __syncthreads();
    if (tid == 0) {
        float ts = 0.f, tss = 0.f;
        for (int i = 0; i < 8; i++) { ts += sm_s[i]; tss += sm_ss[i]; }
        float mean = ts * (1.0f / GN_ELEMS);
        float var  = tss * (1.0f / GN_ELEMS) - mean * mean;
        g_mean[bg] = mean;
        g_rstd[bg] = rsqrtf(var + 1e-6f);
    }
}

// ---------------- zero the rowsum array --------------------------------------
__global__ void zero_rs(float* __restrict__ rs) {
    rs[blockIdx.x * 256 + threadIdx.x] = 0.f;
}

// ---------------- GroupNorm apply + transpose + bf16 split -------------------
__global__ void gn_apply(const float* __restrict__ x,
                         const float* __restrict__ w,
                         const float* __restrict__ b,
                         bf16* __restrict__ hh, bf16* __restrict__ hl) {
    __shared__ float tile[32][33];
    int bb = blockIdx.z, c0 = blockIdx.y * 32, n0 = blockIdx.x * 32;
    int tx = threadIdx.x, ty = threadIdx.y;
#pragma unroll
    for (int i = 0; i < 4; i++) {
        int c = c0 + ty + i * 8;
        int n = n0 + tx;
        float v = x[((size_t)bb * CCH + c) * NPIX + n];
        int g = c >> 3;
        v = (v - g_mean[bb * NGRP + g]) * g_rstd[bb * NGRP + g] * w[c] + b[c];
        tile[ty + i * 8][tx] = v;
    }
    __syncthreads();
#pragma unroll
    for (int i = 0; i < 4; i++) {
        int n = n0 + ty + i * 8;
        int c = c0 + tx;
        float v = tile[tx][ty + i * 8];
        size_t idx = ((size_t)bb * NPIX + n) * CCH + c;
        bf16 h = __float2bfloat16(v);
        hh[idx] = h;
        hl[idx] = __float2bfloat16(v - __bfloat162float(h));
    }
}

// ---------------- split 4 weight matrices ------------------------------------
__global__ void split_weights(const float* __restrict__ q, const float* __restrict__ k,
                              const float* __restrict__ v, const float* __restrict__ o,
                              bf16* __restrict__ wh, bf16* __restrict__ wl) {
    int i = blockIdx.x * 256 + threadIdx.x;
    int mat = i >> 16, off = i & 65535;
    const float* src = (mat == 0) ? q : (mat == 1) ? k : (mat == 2) ? v : o;
    float val = src[off];
    bf16 h = __float2bfloat16(val);
    wh[i] = h;
    wl[i] = __float2bfloat16(val - __bfloat162float(h));
}

// ---------------- transpose+split v: [B,N,C] f32 -> [B,C,N] bf16 hi/lo -------
__global__ void v_transpose(const float* __restrict__ v,
                            bf16* __restrict__ th, bf16* __restrict__ tl) {
    __shared__ float tile[32][33];
    int bb = blockIdx.z, c0 = blockIdx.y * 32, n0 = blockIdx.x * 32;
    int tx = threadIdx.x, ty = threadIdx.y;
#pragma unroll
    for (int i = 0; i < 4; i++) {
        int n = n0 + ty + i * 8;
        tile[ty + i * 8][tx] = v[((size_t)bb * NPIX + n) * CCH + c0 + tx];
    }
    __syncthreads();
#pragma unroll
    for (int i = 0; i < 4; i++) {
        int c = c0 + ty + i * 8;
        int n = n0 + tx;
        float val = tile[tx][ty + i * 8];
        size_t idx = ((size_t)bb * CCH + c) * NPIX + n;
        bf16 h = __float2bfloat16(val);
        th[idx] = h;
        tl[idx] = __float2bfloat16(val - __bfloat162float(h));
    }
}

// ---------------- mma.sync GEMM: C = A @ B^T (+bias) -------------------------
// A [M,K] hi/lo bf16 row-major; B [N,K] hi/lo bf16 row-major.
// EMODE 0: fp32 out (+bias)
// EMODE 1: bf16 hi/lo out (+bias); if rs != nullptr, scale rows by 1/rs[m]
// EMODE 2: exp(acc*SCALE) -> bf16 hi/lo out, row sums atomically added to rs[m]
// 128x128x32 tile, 2-stage cp.async pipeline, 8 warps, 2 CTAs/SM, ldmatrix.
// Compute (Ah+Al)@(Bh+Bl)^T ~= Ah Bh + Ah Bl + Al Bh  (fp32 accumulate).
#define RS     40                   // padded row stride (elems)
#define TERMSZ (128 * RS)           // 5120 elems = 10240 B
#define STAGESZ (4 * TERMSZ)        // elems per stage
#define SMEMSZ (2 * STAGESZ * 2)    // bytes = 81920

template <int EMODE>
__global__ void __launch_bounds__(256, 2)
mma_gemm(const bf16* __restrict__ Ah, const bf16* __restrict__ Al,
         const bf16* __restrict__ Bh, const bf16* __restrict__ Bl,
         const float* __restrict__ bias,
         float* __restrict__ Cf, bf16* __restrict__ Ch, bf16* __restrict__ Cl,
         float* rs,
         int M, int N, int K, long sA, long sB, long sC) {
    extern __shared__ bf16 sm[];
    int tid = threadIdx.x, lane = tid & 31, wid = tid >> 5;
    Ah += (size_t)blockIdx.z * sA;
    Al += (size_t)blockIdx.z * sA;
    Bh += (size_t)blockIdx.z * sB;
    Bl += (size_t)blockIdx.z * sB;
    if (rs) rs += (size_t)blockIdx.z * M;
    size_t coff = (size_t)blockIdx.z * sC;
    int tm = blockIdx.y * 128, tn = blockIdx.x * 128;
    int nk = K >> 5;                       // 32-wide K chunks

    int wm0 = (wid & 1) * 64;              // warp m offset in tile
    int wn0 = (wid >> 1) * 32;             // warp n offset in tile
    int gr = lane >> 2, tc = lane & 3;

    // ldmatrix per-lane row addressing (matrix id = lane>>3)
    int lr = lane & 7, lm = lane >> 3;
    uint32_t rowA = (uint32_t)(wm0 + (lm & 1) * 8 + lr);
    uint32_t kAoff = (uint32_t)((lm >> 1) * 8);
    uint32_t rowB = (uint32_t)(wn0 + (lm >> 1) * 8 + lr);
    uint32_t kBoff = (uint32_t)((lm & 1) * 8);

    uint32_t sb = smem_u32(sm);

    float acc[4][4][4];
#pragma unroll
    for (int i = 0; i < 4; i++)
#pragma unroll
        for (int j = 0; j < 4; j++)
#pragma unroll
            for (int r = 0; r < 4; r++) acc[i][j][r] = 0.f;

    auto load_stage = [&](int chunk) {
        int st = chunk & 1;
        int kb = chunk * 32;
#pragma unroll
        for (int i = 0; i < 8; i++) {
            int c = tid + i * 256;          // 0..2047
            int t = c >> 9;                 // term 0..3
            int idx = c & 511;
            int row = idx >> 2, g = idx & 3;
            const bf16* src = (t == 0) ? Ah : (t == 1) ? Al : (t == 2) ? Bh : Bl;
            int rb = (t < 2) ? tm : tn;
            uint32_t dst = sb + (uint32_t)(st * STAGESZ + t * TERMSZ + row * RS + g * 8) * 2;
            cp_async16(dst, src + ((size_t)(rb + row) * K + kb + g * 8));
        }
        asm volatile("cp.async.commit_group;" ::: "memory");
    };

    load_stage(0);
    if (nk > 1) load_stage(1);

    for (int kt = 0; kt < nk; kt++) {
        if (kt < nk - 1) asm volatile("cp.async.wait_group 1;" ::: "memory");
        else             asm volatile("cp.async.wait_group 0;" ::: "memory");
        __syncthreads();

        uint32_t stage = sb + (uint32_t)((kt & 1) * STAGESZ) * 2;
        uint32_t sAh = stage;
        uint32_t sAl = stage + TERMSZ * 2;
        uint32_t sBh = stage + 2 * TERMSZ * 2;
        uint32_t sBl = stage + 3 * TERMSZ * 2;

#pragma unroll
        for (int kk = 0; kk < 2; kk++) {
            uint32_t k0 = (uint32_t)(kk * 16);
            uint32_t bh[4][2], bl[4][2];
#pragma unroll
            for (int p = 0; p < 2; p++) {
                uint32_t boff = ((rowB + p * 16) * RS + k0 + kBoff) * 2;
                ldsm_x4(sBh + boff, &bh[p * 2][0]);
                ldsm_x4(sBl + boff, &bl[p * 2][0]);
            }
#pragma unroll
            for (int mi = 0; mi < 4; mi++) {
                uint32_t aoff = ((rowA + mi * 16) * RS + k0 + kAoff) * 2;
                uint32_t ah[4], al[4];
                ldsm_x4(sAh + aoff, ah);
                ldsm_x4(sAl + aoff, al);
#pragma unroll
                for (int ni = 0; ni < 4; ni++) {
                    mma16816(acc[mi][ni], ah, bh[ni]);
                    mma16816(acc[mi][ni], ah, bl[ni]);
                    mma16816(acc[mi][ni], al, bh[ni]);
                }
            }
        }
        __syncthreads();
        if (kt + 2 < nk) load_stage(kt + 2);
    }

    // ---------------- epilogue ----------------
    if (EMODE == 2) {
        // exp + rowsum + bf16-pair store of unnormalized probabilities
#pragma unroll
        for (int mi = 0; mi < 4; mi++) {
            float s0 = 0.f, s1 = 0.f;
#pragma unroll
            for (int ni = 0; ni < 4; ni++) {
                acc[mi][ni][0] = __expf(acc[mi][ni][0] * SCALE);
                acc[mi][ni][1] = __expf(acc[mi][ni][1] * SCALE);
                acc[mi][ni][2] = __expf(acc[mi][ni][2] * SCALE);
                acc[mi][ni][3] = __expf(acc[mi][ni][3] * SCALE);
                s0 += acc[mi][ni][0] + acc[mi][ni][1];
                s1 += acc[mi][ni][2] + acc[mi][ni][3];
            }
            // reduce over the 4 lanes (tc) sharing each row
            s0 += __shfl_xor_sync(0xffffffffu, s0, 1);
            s0 += __shfl_xor_sync(0xffffffffu, s0, 2);
            s1 += __shfl_xor_sync(0xffffffffu, s1, 1);
            s1 += __shfl_xor_sync(0xffffffffu, s1, 2);
            if (tc == 0) {
                int r = tm + wm0 + mi * 16 + gr;
                atomicAdd(&rs[r], s0);
                atomicAdd(&rs[r + 8], s1);
            }
        }
    }

#pragma unroll
    for (int mi = 0; mi < 4; mi++) {
        float inv0 = 1.f, inv1 = 1.f;
        if (EMODE == 1 && rs) {
            int r = tm + wm0 + mi * 16 + gr;
            inv0 = 1.0f / rs[r];
            inv1 = 1.0f / rs[r + 8];
        }
#pragma unroll
        for (int ni = 0; ni < 4; ni++) {
            int m = tm + wm0 + mi * 16 + gr;
            int n = tn + wn0 + ni * 8 + tc * 2;
            float b0v = (EMODE != 2 && bias) ? bias[n]     : 0.f;
            float b1v = (EMODE != 2 && bias) ? bias[n + 1] : 0.f;
            float c0 = acc[mi][ni][0] * inv0 + b0v, c1 = acc[mi][ni][1] * inv0 + b1v;
            float c2 = acc[mi][ni][2] * inv1 + b0v, c3 = acc[mi][ni][3] * inv1 + b1v;
            if (EMODE == 0) {
                float2 v0 = {c0, c1}, v1 = {c2, c3};
                *(float2*)&Cf[coff + (size_t)m * N + n]       = v0;
                *(float2*)&Cf[coff + (size_t)(m + 8) * N + n] = v1;
            } else {
                bf16 h0 = __float2bfloat16(c0), h1 = __float2bfloat16(c1);
                bf16 h2 = __float2bfloat16(c2), h3 = __float2bfloat16(c3);
                uint32_t hi0 = (uint32_t)__bfloat16_as_ushort(h0) |
                               ((uint32_t)__bfloat16_as_ushort(h1) << 16);
                uint32_t hi1 = (uint32_t)__bfloat16_as_ushort(h2) |
                               ((uint32_t)__bfloat16_as_ushort(h3) << 16);
                uint32_t lo0 = pack_bf2(c0 - __bfloat162float(h0), c1 - __bfloat162float(h1));
                uint32_t lo1 = pack_bf2(c2 - __bfloat162float(h2), c3 - __bfloat162float(h3));
                *(uint32_t*)&Ch[coff + (size_t)m * N + n]       = hi0;
                *(uint32_t*)&Ch[coff + (size_t)(m + 8) * N + n] = hi1;
                *(uint32_t*)&Cl[coff + (size_t)m * N + n]       = lo0;
                *(uint32_t*)&Cl[coff + (size_t)(m + 8) * N + n] = lo1;
            }
        }
    }
}

// ---------------- final: y = (x + tmp^T) * 1/sqrt(2) -------------------------
__global__ void final_residual(const float* __restrict__ x,
                               const float* __restrict__ tmp,
                               float* __restrict__ y) {
    __shared__ float tile[32][33];
    int bb = blockIdx.z, c0 = blockIdx.y * 32, n0 = blockIdx.x * 32;
    int tx = threadIdx.x, ty = threadIdx.y;
#pragma unroll
    for (int i = 0; i < 4; i++) {
        int n = n0 + ty + i * 8;
        tile[ty + i * 8][tx] = tmp[((size_t)bb * NPIX + n) * CCH + c0 + tx];
    }
    __syncthreads();
#pragma unroll
    for (int i = 0; i < 4; i++) {
        int c = c0 + ty + i * 8;
        int n = n0 + tx;
        size_t idx = ((size_t)bb * CCH + c) * NPIX + n;
        y[idx] = (x[idx] + tile[tx][ty + i * 8]) * INV_SQRT2;
    }
}

// ---------------- launch ------------------------------------------------------
extern "C" void kernel_launch(void* const* d_in, const int* in_sizes, int n_in,
                              void* d_out, int out_size) {
    const float* x  = (const float*)d_in[0];
    const float* gw = (const float*)d_in[1];
    const float* gb = (const float*)d_in[2];
    const float* Wq = (const float*)d_in[3];
    const float* bq = (const float*)d_in[4];
    const float* Wk = (const float*)d_in[5];
    const float* bk = (const float*)d_in[6];
    const float* Wv = (const float*)d_in[7];
    const float* bv = (const float*)d_in[8];
    const float* Wo = (const float*)d_in[9];
    const float* bo = (const float*)d_in[10];
    float* y = (float*)d_out;

    cudaFuncSetAttribute(mma_gemm<0>, cudaFuncAttributeMaxDynamicSharedMemorySize, SMEMSZ);
    cudaFuncSetAttribute(mma_gemm<1>, cudaFuncAttributeMaxDynamicSharedMemorySize, SMEMSZ);
    cudaFuncSetAttribute(mma_gemm<2>, cudaFuncAttributeMaxDynamicSharedMemorySize, SMEMSZ);

    bf16 *hs_h, *hs_l, *q_h, *q_l, *k_h, *k_l, *vt_h, *vt_l, *p_h, *p_l, *ao_h, *ao_l, *w_h, *w_l;
    float *v, *tmp, *rsum;
    cudaGetSymbolAddress((void**)&hs_h, g_hs_h);
    cudaGetSymbolAddress((void**)&hs_l, g_hs_l);
    cudaGetSymbolAddress((void**)&q_h,  g_q_h);
    cudaGetSymbolAddress((void**)&q_l,  g_q_l);
    cudaGetSymbolAddress((void**)&k_h,  g_k_h);
    cudaGetSymbolAddress((void**)&k_l,  g_k_l);
    cudaGetSymbolAddress((void**)&v,    g_v);
    cudaGetSymbolAddress((void**)&vt_h, g_vt_h);
    cudaGetSymbolAddress((void**)&vt_l, g_vt_l);
    cudaGetSymbolAddress((void**)&p_h,  g_p_h);
    cudaGetSymbolAddress((void**)&p_l,  g_p_l);
    cudaGetSymbolAddress((void**)&ao_h, g_ao_h);
    cudaGetSymbolAddress((void**)&ao_l, g_ao_l);
    cudaGetSymbolAddress((void**)&tmp,  g_tmp);
    cudaGetSymbolAddress((void**)&w_h,  g_w_h);
    cudaGetSymbolAddress((void**)&w_l,  g_w_l);
    cudaGetSymbolAddress((void**)&rsum, g_rowsum);

    const long NC = (long)NPIX * CCH;
    const long NN = (long)NPIX * NPIX;
    const int  MALL = BATCH * NPIX;   // 16384

    gn_stats<<<BATCH * NGRP, 256>>>(x);
    zero_rs<<<(BATCH * NPIX) / 256, 256>>>(rsum);
    gn_apply<<<dim3(NPIX / 32, CCH / 32, BATCH), dim3(32, 8)>>>(x, gw, gb, hs_h, hs_l);
    split_weights<<<1024, 256>>>(Wq, Wk, Wv, Wo, w_h, w_l);

    // QKV projections: [16384,256] @ W^T + b
    mma_gemm<1><<<dim3(2, MALL / 128, 1), 256, SMEMSZ>>>(
        hs_h, hs_l, w_h, w_l, bq, nullptr, q_h, q_l, nullptr, MALL, CCH, CCH, 0, 0, 0);
    mma_gemm<1><<<dim3(2, MALL / 128, 1), 256, SMEMSZ>>>(
        hs_h, hs_l, w_h + 65536, w_l + 65536, bk, nullptr, k_h, k_l, nullptr, MALL, CCH, CCH, 0, 0, 0);
    mma_gemm<0><<<dim3(2, MALL / 128, 1), 256, SMEMSZ>>>(
        hs_h, hs_l, w_h + 131072, w_l + 131072, bv, v, nullptr, nullptr, nullptr, MALL, CCH, CCH, 0, 0, 0);
    v_transpose<<<dim3(NPIX / 32, CCH / 32, BATCH), dim3(32, 8)>>>(v, vt_h, vt_l);

    // S = Q @ K^T (batched): epilogue computes exp + rowsums, writes bf16 pair
    mma_gemm<2><<<dim3(32, 32, BATCH), 256, SMEMSZ>>>(
        q_h, q_l, k_h, k_l, nullptr, nullptr, p_h, p_l, rsum, NPIX, NPIX, CCH, NC, NC, NN);

    // AO = (P @ V) / rowsum  (B operand = V^T as [C,N] K-major)
    mma_gemm<1><<<dim3(2, 32, BATCH), 256, SMEMSZ>>>(
        p_h, p_l, vt_h, vt_l, nullptr, nullptr, ao_h, ao_l, rsum, NPIX, CCH, NPIX, NN, NC, NC);

    // O projection
    mma_gemm<0><<<dim3(2, MALL / 128, 1), 256, SMEMSZ>>>(
        ao_h, ao_l, w_h + 196608, w_l + 196608, bo, tmp, nullptr, nullptr, nullptr, MALL, CCH, CCH, 0, 0, 0);

    final_residual<<<dim3(NPIX / 32, CCH / 32, BATCH), dim3(32, 8)>>>(x, tmp, y);
}

// round 7
// speedup vs baseline: 2.9477x; 1.2524x over previous
#include <cuda_runtime.h>
#include <cuda_fp16.h>
#include <math_constants.h>
#include <cstdint>

typedef __half f16;

#define BATCH 4
#define CCH   256
#define NPIX  4096
#define NGRP  32
#define GN_ELEMS (8 * NPIX)
#define SCALE 0.0625f
#define ESHIFT 4.0f
#define INV_SQRT2 0.70710678118654752f

#define NELT (BATCH * NPIX * CCH)            // 4,194,304
#define NNELT ((size_t)BATCH * NPIX * NPIX)  // 67,108,864

// ---------------- scratch (device globals) ---------------------------------
__device__ f16   g_hs_h[NELT], g_hs_l[NELT];
__device__ f16   g_q_h [NELT], g_q_l [NELT];
__device__ f16   g_k   [NELT];                   // single fp16
__device__ float g_v   [NELT];
__device__ f16   g_vt  [NELT];                   // single fp16, [B,C,N]
__device__ f16   g_p_h [NNELT], g_p_l[NNELT];    // unnormalized shifted exp
__device__ f16   g_ao_h[NELT], g_ao_l[NELT];
__device__ float g_tmp [NELT];
__device__ f16   g_w_h [4 * CCH * CCH], g_w_l[4 * CCH * CCH];
__device__ float g_mean[BATCH * NGRP], g_rstd[BATCH * NGRP];
__device__ float g_rowsum[BATCH * NPIX];

// ---------------- helpers ----------------------------------------------------
__device__ __forceinline__ uint32_t smem_u32(const void* p) {
    uint32_t a;
    asm("{ .reg .u64 t; cvta.to.shared.u64 t, %1; cvt.u32.u64 %0, t; }"
        : "=r"(a) : "l"(p));
    return a;
}
__device__ __forceinline__ void cp_async16(uint32_t dst, const void* src) {
    asm volatile("cp.async.cg.shared.global [%0], [%1], 16;" :: "r"(dst), "l"(src));
}
__device__ __forceinline__ void ldsm_x4(uint32_t addr, uint32_t* r) {
    asm volatile("ldmatrix.sync.aligned.m8n8.x4.shared.b16 {%0,%1,%2,%3}, [%4];"
                 : "=r"(r[0]), "=r"(r[1]), "=r"(r[2]), "=r"(r[3]) : "r"(addr));
}
__device__ __forceinline__ void mma16816(float* c, const uint32_t* a, const uint32_t* b) {
    asm volatile(
        "mma.sync.aligned.m16n8k16.row.col.f32.f16.f16.f32 "
        "{%0,%1,%2,%3}, {%4,%5,%6,%7}, {%8,%9}, {%0,%1,%2,%3};"
        : "+f"(c[0]), "+f"(c[1]), "+f"(c[2]), "+f"(c[3])
        : "r"(a[0]), "r"(a[1]), "r"(a[2]), "r"(a[3]), "r"(b[0]), "r"(b[1]));
}
__device__ __forceinline__ uint32_t pack_h2(float f0, float f1) {
    uint32_t u0 = (uint32_t)__half_as_ushort(__float2half_rn(f0));
    uint32_t u1 = (uint32_t)__half_as_ushort(__float2half_rn(f1));
    return u0 | (u1 << 16);
}
__device__ __forceinline__ void split_h(float v, f16& h, f16& l) {
    h = __float2half_rn(v);
    l = __float2half_rn(v - __half2float(h));
}

// ---------------- GroupNorm statistics --------------------------------------
__global__ void gn_stats(const float* __restrict__ x) {
    int bg = blockIdx.x;
    const float* px = x + (size_t)bg * GN_ELEMS;
    int tid = threadIdx.x;
    float s = 0.f, ss = 0.f;
    for (int i = tid; i < GN_ELEMS; i += 256) {
        float v = px[i];
        s += v; ss += v * v;
    }
    for (int o = 16; o; o >>= 1) {
        s  += __shfl_xor_sync(0xffffffffu, s, o);
        ss += __shfl_xor_sync(0xffffffffu, ss, o);
    }
    __shared__ float sm_s[8], sm_ss[8];
    int lane = tid & 31, warp = tid >> 5;
    if (lane == 0) { sm_s[warp] = s; sm_ss[warp] = ss; }
    __syncthreads();
    if (tid == 0) {
        float ts = 0.f, tss = 0.f;
        for (int i = 0; i < 8; i++) { ts += sm_s[i]; tss += sm_ss[i]; }
        float mean = ts * (1.0f / GN_ELEMS);
        float var  = tss * (1.0f / GN_ELEMS) - mean * mean;
        g_mean[bg] = mean;
        g_rstd[bg] = rsqrtf(var + 1e-6f);
    }
}

// ---------------- zero the rowsum array --------------------------------------
__global__ void zero_rs(float* __restrict__ rs) {
    rs[blockIdx.x * 256 + threadIdx.x] = 0.f;
}

// ---------------- GroupNorm apply + transpose + fp16 split -------------------
__global__ void gn_apply(const float* __restrict__ x,
                         const float* __restrict__ w,
                         const float* __restrict__ b,
                         f16* __restrict__ hh, f16* __restrict__ hl) {
    __shared__ float tile[32][33];
    int bb = blockIdx.z, c0 = blockIdx.y * 32, n0 = blockIdx.x * 32;
    int tx = threadIdx.x, ty = threadIdx.y;
#pragma unroll
    for (int i = 0; i < 4; i++) {
        int c = c0 + ty + i * 8;
        int n = n0 + tx;
        float v = x[((size_t)bb * CCH + c) * NPIX + n];
        int g = c >> 3;
        v = (v - g_mean[bb * NGRP + g]) * g_rstd[bb * NGRP + g] * w[c] + b[c];
        tile[ty + i * 8][tx] = v;
    }
    __syncthreads();
#pragma unroll
    for (int i = 0; i < 4; i++) {
        int n = n0 + ty + i * 8;
        int c = c0 + tx;
        float v = tile[tx][ty + i * 8];
        size_t idx = ((size_t)bb * NPIX + n) * CCH + c;
        f16 h, l; split_h(v, h, l);
        hh[idx] = h;
        hl[idx] = l;
    }
}

// ---------------- split 4 weight matrices ------------------------------------
__global__ void split_weights(const float* __restrict__ q, const float* __restrict__ k,
                              const float* __restrict__ v, const float* __restrict__ o,
                              f16* __restrict__ wh, f16* __restrict__ wl) {
    int i = blockIdx.x * 256 + threadIdx.x;
    int mat = i >> 16, off = i & 65535;
    const float* src = (mat == 0) ? q : (mat == 1) ? k : (mat == 2) ? v : o;
    float val = src[off];
    f16 h, l; split_h(val, h, l);
    wh[i] = h;
    wl[i] = l;
}

// ---------------- transpose v: [B,N,C] f32 -> [B,C,N] single fp16 ------------
__global__ void v_transpose(const float* __restrict__ v, f16* __restrict__ t) {
    __shared__ float tile[32][33];
    int bb = blockIdx.z, c0 = blockIdx.y * 32, n0 = blockIdx.x * 32;
    int tx = threadIdx.x, ty = threadIdx.y;
#pragma unroll
    for (int i = 0; i < 4; i++) {
        int n = n0 + ty + i * 8;
        tile[ty + i * 8][tx] = v[((size_t)bb * NPIX + n) * CCH + c0 + tx];
    }
    __syncthreads();
#pragma unroll
    for (int i = 0; i < 4; i++) {
        int c = c0 + ty + i * 8;
        int n = n0 + tx;
        t[((size_t)bb * CCH + c) * NPIX + n] = __float2half_rn(tile[tx][ty + i * 8]);
    }
}

// ---------------- mma.sync GEMM: C = A @ B^T (+bias) -------------------------
// A [M,K] hi/lo fp16 row-major; B [N,K] fp16 row-major (hi [+lo if NTB=2]).
// NTB=2: 3 MMAs/k16 (AhBh+AhBl+AlBh), 2 stages.  NTB=1: 2 MMAs (AhB+AlB), 3 stages.
// EMODE 0: fp32 out (+bias)
// EMODE 1: fp16 hi/lo out (+bias); if rs: rows scaled by 1/rs[m]
// EMODE 2: exp(acc*SCALE-ESHIFT) -> fp16 hi/lo, rowsums atomically added to rs
// EMODE 3: fp16 single out (+bias)
// 128x128x32 tile, cp.async pipeline, 8 warps, 2 CTAs/SM, ldmatrix.
#define RS     40                   // padded row stride (elems)
#define TERMSZ (128 * RS)           // 5120 elems = 10240 B

template <int EMODE, int NTB>
__global__ void __launch_bounds__(256, 2)
mma_gemm(const f16* __restrict__ Ah, const f16* __restrict__ Al,
         const f16* __restrict__ Bh, const f16* __restrict__ Bl,
         const float* __restrict__ bias,
         float* __restrict__ Cf, f16* __restrict__ Ch, f16* __restrict__ Cl,
         float* rs,
         int M, int N, int K, long sA, long sB, long sC) {
    constexpr int NTERMS = 2 + NTB;
    constexpr int NSTAGE = (NTB == 1) ? 3 : 2;
    constexpr int STAGEELEMS = NTERMS * TERMSZ;
    extern __shared__ f16 sm[];
    int tid = threadIdx.x, lane = tid & 31, wid = tid >> 5;
    Ah += (size_t)blockIdx.z * sA;
    Al += (size_t)blockIdx.z * sA;
    Bh += (size_t)blockIdx.z * sB;
    if (NTB == 2) Bl += (size_t)blockIdx.z * sB;
    if (rs) rs += (size_t)blockIdx.z * M;
    size_t coff = (size_t)blockIdx.z * sC;
    int tm = blockIdx.y * 128, tn = blockIdx.x * 128;
    int nk = K >> 5;

    int wm0 = (wid & 1) * 64;
    int wn0 = (wid >> 1) * 32;
    int gr = lane >> 2, tc = lane & 3;

    int lr = lane & 7, lm = lane >> 3;
    uint32_t rowA = (uint32_t)(wm0 + (lm & 1) * 8 + lr);
    uint32_t kAoff = (uint32_t)((lm >> 1) * 8);
    uint32_t rowB = (uint32_t)(wn0 + (lm >> 1) * 8 + lr);
    uint32_t kBoff = (uint32_t)((lm & 1) * 8);

    uint32_t sb = smem_u32(sm);

    float acc[4][4][4];
#pragma unroll
    for (int i = 0; i < 4; i++)
#pragma unroll
        for (int j = 0; j < 4; j++)
#pragma unroll
            for (int r = 0; r < 4; r++) acc[i][j][r] = 0.f;

    auto load_stage = [&](int chunk) {
        int st = chunk % NSTAGE;
        int kb = chunk * 32;
#pragma unroll
        for (int i = 0; i < NTERMS * 2; i++) {
            int c = tid + i * 256;
            int t = c >> 9;                 // term index
            int idx = c & 511;
            int row = idx >> 2, g = idx & 3;
            const f16* src = (t == 0) ? Ah : (t == 1) ? Al : (t == 2) ? Bh : Bl;
            int rb = (t < 2) ? tm : tn;
            uint32_t dst = sb + (uint32_t)(st * STAGEELEMS + t * TERMSZ + row * RS + g * 8) * 2;
            cp_async16(dst, src + ((size_t)(rb + row) * K + kb + g * 8));
        }
        asm volatile("cp.async.commit_group;" ::: "memory");
    };

    load_stage(0);
    if (nk > 1) load_stage(1);

    for (int kt = 0; kt < nk; kt++) {
        if (kt < nk - 1) asm volatile("cp.async.wait_group 1;" ::: "memory");
        else             asm volatile("cp.async.wait_group 0;" ::: "memory");
        __syncthreads();

        uint32_t stage = sb + (uint32_t)((kt % NSTAGE) * STAGEELEMS) * 2;
        uint32_t sAh = stage;
        uint32_t sAl = stage + TERMSZ * 2;
        uint32_t sBh = stage + 2 * TERMSZ * 2;
        uint32_t sBl = stage + 3 * TERMSZ * 2;

#pragma unroll
        for (int kk = 0; kk < 2; kk++) {
            uint32_t k0 = (uint32_t)(kk * 16);
            uint32_t bh[4][2], bl[4][2];
#pragma unroll
            for (int p = 0; p < 2; p++) {
                uint32_t boff = ((rowB + p * 16) * RS + k0 + kBoff) * 2;
                ldsm_x4(sBh + boff, &bh[p * 2][0]);
                if (NTB == 2) ldsm_x4(sBl + boff, &bl[p * 2][0]);
            }
#pragma unroll
            for (int mi = 0; mi < 4; mi++) {
                uint32_t aoff = ((rowA + mi * 16) * RS + k0 + kAoff) * 2;
                uint32_t ah[4], al[4];
                ldsm_x4(sAh + aoff, ah);
                ldsm_x4(sAl + aoff, al);
#pragma unroll
                for (int ni = 0; ni < 4; ni++) {
                    mma16816(acc[mi][ni], ah, bh[ni]);
                    mma16816(acc[mi][ni], al, bh[ni]);
                    if (NTB == 2) mma16816(acc[mi][ni], ah, bl[ni]);
                }
            }
        }
        __syncthreads();
        if (kt + 2 < nk) load_stage(kt + 2);
    }

    // ---------------- epilogue ----------------
    if (EMODE == 2) {
#pragma unroll
        for (int mi = 0; mi < 4; mi++) {
            float s0 = 0.f, s1 = 0.f;
#pragma unroll
            for (int ni = 0; ni < 4; ni++) {
                acc[mi][ni][0] = __expf(acc[mi][ni][0] * SCALE - ESHIFT);
                acc[mi][ni][1] = __expf(acc[mi][ni][1] * SCALE - ESHIFT);
                acc[mi][ni][2] = __expf(acc[mi][ni][2] * SCALE - ESHIFT);
                acc[mi][ni][3] = __expf(acc[mi][ni][3] * SCALE - ESHIFT);
                s0 += acc[mi][ni][0] + acc[mi][ni][1];
                s1 += acc[mi][ni][2] + acc[mi][ni][3];
            }
            s0 += __shfl_xor_sync(0xffffffffu, s0, 1);
            s0 += __shfl_xor_sync(0xffffffffu, s0, 2);
            s1 += __shfl_xor_sync(0xffffffffu, s1, 1);
            s1 += __shfl_xor_sync(0xffffffffu, s1, 2);
            if (tc == 0) {
                int r = tm + wm0 + mi * 16 + gr;
                atomicAdd(&rs[r], s0);
                atomicAdd(&rs[r + 8], s1);
            }
        }
    }

#pragma unroll
    for (int mi = 0; mi < 4; mi++) {
        float inv0 = 1.f, inv1 = 1.f;
        if (EMODE == 1 && rs) {
            int r = tm + wm0 + mi * 16 + gr;
            inv0 = 1.0f / rs[r];
            inv1 = 1.0f / rs[r + 8];
        }
#pragma unroll
        for (int ni = 0; ni < 4; ni++) {
            int m = tm + wm0 + mi * 16 + gr;
            int n = tn + wn0 + ni * 8 + tc * 2;
            float b0v = (EMODE != 2 && bias) ? bias[n]     : 0.f;
            float b1v = (EMODE != 2 && bias) ? bias[n + 1] : 0.f;
            float c0 = acc[mi][ni][0] * inv0 + b0v, c1 = acc[mi][ni][1] * inv0 + b1v;
            float c2 = acc[mi][ni][2] * inv1 + b0v, c3 = acc[mi][ni][3] * inv1 + b1v;
            if (EMODE == 0) {
                float2 v0 = {c0, c1}, v1 = {c2, c3};
                *(float2*)&Cf[coff + (size_t)m * N + n]       = v0;
                *(float2*)&Cf[coff + (size_t)(m + 8) * N + n] = v1;
            } else if (EMODE == 3) {
                *(uint32_t*)&Ch[coff + (size_t)m * N + n]       = pack_h2(c0, c1);
                *(uint32_t*)&Ch[coff + (size_t)(m + 8) * N + n] = pack_h2(c2, c3);
            } else {
                f16 h0 = __float2half_rn(c0), h1 = __float2half_rn(c1);
                f16 h2 = __float2half_rn(c2), h3 = __float2half_rn(c3);
                uint32_t hi0 = (uint32_t)__half_as_ushort(h0) |
                               ((uint32_t)__half_as_ushort(h1) << 16);
                uint32_t hi1 = (uint32_t)__half_as_ushort(h2) |
                               ((uint32_t)__half_as_ushort(h3) << 16);
                uint32_t lo0 = pack_h2(c0 - __half2float(h0), c1 - __half2float(h1));
                uint32_t lo1 = pack_h2(c2 - __half2float(h2), c3 - __half2float(h3));
                *(uint32_t*)&Ch[coff + (size_t)m * N + n]       = hi0;
                *(uint32_t*)&Ch[coff + (size_t)(m + 8) * N + n] = hi1;
                *(uint32_t*)&Cl[coff + (size_t)m * N + n]       = lo0;
                *(uint32_t*)&Cl[coff + (size_t)(m + 8) * N + n] = lo1;
            }
        }
    }
}

// ---------------- final: y = (x + tmp^T) * 1/sqrt(2) -------------------------
__global__ void final_residual(const float* __restrict__ x,
                               const float* __restrict__ tmp,
                               float* __restrict__ y) {
    __shared__ float tile[32][33];
    int bb = blockIdx.z, c0 = blockIdx.y * 32, n0 = blockIdx.x * 32;
    int tx = threadIdx.x, ty = threadIdx.y;
#pragma unroll
    for (int i = 0; i < 4; i++) {
        int n = n0 + ty + i * 8;
        tile[ty + i * 8][tx] = tmp[((size_t)bb * NPIX + n) * CCH + c0 + tx];
    }
    __syncthreads();
#pragma unroll
    for (int i = 0; i < 4; i++) {
        int c = c0 + ty + i * 8;
        int n = n0 + tx;
        size_t idx = ((size_t)bb * CCH + c) * NPIX + n;
        y[idx] = (x[idx] + tile[tx][ty + i * 8]) * INV_SQRT2;
    }
}

// ---------------- launch ------------------------------------------------------
#define SMEM_3T (2 * 4 * TERMSZ * 2)   // 81920 B  (NTB=2, 2 stages)
#define SMEM_2T (3 * 3 * TERMSZ * 2)   // 92160 B  (NTB=1, 3 stages)

extern "C" void kernel_launch(void* const* d_in, const int* in_sizes, int n_in,
                              void* d_out, int out_size) {
    const float* x  = (const float*)d_in[0];
    const float* gw = (const float*)d_in[1];
    const float* gb = (const float*)d_in[2];
    const float* Wq = (const float*)d_in[3];
    const float* bq = (const float*)d_in[4];
    const float* Wk = (const float*)d_in[5];
    const float* bk = (const float*)d_in[6];
    const float* Wv = (const float*)d_in[7];
    const float* bv = (const float*)d_in[8];
    const float* Wo = (const float*)d_in[9];
    const float* bo = (const float*)d_in[10];
    float* y = (float*)d_out;

    cudaFuncSetAttribute(mma_gemm<0, 2>, cudaFuncAttributeMaxDynamicSharedMemorySize, SMEM_3T);
    cudaFuncSetAttribute(mma_gemm<1, 2>, cudaFuncAttributeMaxDynamicSharedMemorySize, SMEM_3T);
    cudaFuncSetAttribute(mma_gemm<3, 2>, cudaFuncAttributeMaxDynamicSharedMemorySize, SMEM_3T);
    cudaFuncSetAttribute(mma_gemm<2, 1>, cudaFuncAttributeMaxDynamicSharedMemorySize, SMEM_2T);
    cudaFuncSetAttribute(mma_gemm<1, 1>, cudaFuncAttributeMaxDynamicSharedMemorySize, SMEM_2T);

    f16 *hs_h, *hs_l, *q_h, *q_l, *k1, *vt, *p_h, *p_l, *ao_h, *ao_l, *w_h, *w_l;
    float *v, *tmp, *rsum;
    cudaGetSymbolAddress((void**)&hs_h, g_hs_h);
    cudaGetSymbolAddress((void**)&hs_l, g_hs_l);
    cudaGetSymbolAddress((void**)&q_h,  g_q_h);
    cudaGetSymbolAddress((void**)&q_l,  g_q_l);
    cudaGetSymbolAddress((void**)&k1,   g_k);
    cudaGetSymbolAddress((void**)&v,    g_v);
    cudaGetSymbolAddress((void**)&vt,   g_vt);
    cudaGetSymbolAddress((void**)&p_h,  g_p_h);
    cudaGetSymbolAddress((void**)&p_l,  g_p_l);
    cudaGetSymbolAddress((void**)&ao_h, g_ao_h);
    cudaGetSymbolAddress((void**)&ao_l, g_ao_l);
    cudaGetSymbolAddress((void**)&tmp,  g_tmp);
    cudaGetSymbolAddress((void**)&w_h,  g_w_h);
    cudaGetSymbolAddress((void**)&w_l,  g_w_l);
    cudaGetSymbolAddress((void**)&rsum, g_rowsum);

    const long NC = (long)NPIX * CCH;
    const long NN = (long)NPIX * NPIX;
    const int  MALL = BATCH * NPIX;   // 16384

    gn_stats<<<BATCH * NGRP, 256>>>(x);
    zero_rs<<<(BATCH * NPIX) / 256, 256>>>(rsum);
    gn_apply<<<dim3(NPIX / 32, CCH / 32, BATCH), dim3(32, 8)>>>(x, gw, gb, hs_h, hs_l);
    split_weights<<<1024, 256>>>(Wq, Wk, Wv, Wo, w_h, w_l);

    // Q projection -> fp16 hi/lo
    mma_gemm<1, 2><<<dim3(2, MALL / 128, 1), 256, SMEM_3T>>>(
        hs_h, hs_l, w_h, w_l, bq, nullptr, q_h, q_l, nullptr, MALL, CCH, CCH, 0, 0, 0);
    // K projection -> fp16 single
    mma_gemm<3, 2><<<dim3(2, MALL / 128, 1), 256, SMEM_3T>>>(
        hs_h, hs_l, w_h + 65536, w_l + 65536, bk, nullptr, k1, nullptr, nullptr, MALL, CCH, CCH, 0, 0, 0);
    // V projection -> fp32, then transpose -> fp16 single [B,C,N]
    mma_gemm<0, 2><<<dim3(2, MALL / 128, 1), 256, SMEM_3T>>>(
        hs_h, hs_l, w_h + 131072, w_l + 131072, bv, v, nullptr, nullptr, nullptr, MALL, CCH, CCH, 0, 0, 0);
    v_transpose<<<dim3(NPIX / 32, CCH / 32, BATCH), dim3(32, 8)>>>(v, vt);

    // S = Q @ K^T (2-term): epilogue exp(+shift) + rowsums, writes fp16 pair
    mma_gemm<2, 1><<<dim3(32, 32, BATCH), 256, SMEM_2T>>>(
        q_h, q_l, k1, nullptr, nullptr, nullptr, p_h, p_l, rsum, NPIX, NPIX, CCH, NC, NC, NN);

    // AO = (P @ V) / rowsum (2-term)
    mma_gemm<1, 1><<<dim3(2, 32, BATCH), 256, SMEM_2T>>>(
        p_h, p_l, vt, nullptr, nullptr, nullptr, ao_h, ao_l, rsum, NPIX, CCH, NPIX, NN, NC, NC);

    // O projection -> fp32
    mma_gemm<0, 2><<<dim3(2, MALL / 128, 1), 256, SMEM_3T>>>(
        ao_h, ao_l, w_h + 196608, w_l + 196608, bo, tmp, nullptr, nullptr, nullptr, MALL, CCH, CCH, 0, 0, 0);

    final_residual<<<dim3(NPIX / 32, CCH / 32, BATCH), dim3(32, 8)>>>(x, tmp, y);
}

// round 8
// speedup vs baseline: 4.4705x; 1.5166x over previous
#include <cuda_runtime.h>
#include <cuda_fp16.h>
#include <math_constants.h>
#include <cstdint>

typedef __half f16;

#define BATCH 4
#define CCH   256
#define NPIX  4096
#define NGRP  32
#define GN_ELEMS (8 * NPIX)
#define SCALE 0.0625f
#define ESHIFT 4.0f
#define INV_SQRT2 0.70710678118654752f

#define NELT (BATCH * NPIX * CCH)            // 4,194,304
#define NNELT ((size_t)BATCH * NPIX * NPIX)  // 67,108,864

// ---------------- scratch (device globals) ---------------------------------
__device__ f16   g_hs_h[NELT], g_hs_l[NELT];
__device__ f16   g_q   [NELT];                   // single fp16
__device__ f16   g_k   [NELT];                   // single fp16
__device__ float g_v   [NELT];
__device__ f16   g_vt  [NELT];                   // single fp16, [B,C,N]
__device__ f16   g_p   [NNELT];                  // single fp16 unnormalized exp
__device__ f16   g_ao_h[NELT], g_ao_l[NELT];
__device__ float g_tmp [NELT];
__device__ f16   g_w_h [4 * CCH * CCH], g_w_l[4 * CCH * CCH];
__device__ float g_mean[BATCH * NGRP], g_rstd[BATCH * NGRP];
__device__ float g_rowsum[BATCH * NPIX];

// ---------------- helpers ----------------------------------------------------
__device__ __forceinline__ uint32_t smem_u32(const void* p) {
    uint32_t a;
    asm("{ .reg .u64 t; cvta.to.shared.u64 t, %1; cvt.u32.u64 %0, t; }"
        : "=r"(a) : "l"(p));
    return a;
}
__device__ __forceinline__ void cp_async16(uint32_t dst, const void* src) {
    asm volatile("cp.async.cg.shared.global [%0], [%1], 16;" :: "r"(dst), "l"(src));
}
template <int N>
__device__ __forceinline__ void cp_wait() {
    asm volatile("cp.async.wait_group %0;" :: "n"(N) : "memory");
}
__device__ __forceinline__ void ldsm_x4(uint32_t addr, uint32_t* r) {
    asm volatile("ldmatrix.sync.aligned.m8n8.x4.shared.b16 {%0,%1,%2,%3}, [%4];"
                 : "=r"(r[0]), "=r"(r[1]), "=r"(r[2]), "=r"(r[3]) : "r"(addr));
}
__device__ __forceinline__ void mma16816(float* c, const uint32_t* a, const uint32_t* b) {
    asm volatile(
        "mma.sync.aligned.m16n8k16.row.col.f32.f16.f16.f32 "
        "{%0,%1,%2,%3}, {%4,%5,%6,%7}, {%8,%9}, {%0,%1,%2,%3};"
        : "+f"(c[0]), "+f"(c[1]), "+f"(c[2]), "+f"(c[3])
        : "r"(a[0]), "r"(a[1]), "r"(a[2]), "r"(a[3]), "r"(b[0]), "r"(b[1]));
}
__device__ __forceinline__ uint32_t pack_h2(float f0, float f1) {
    uint32_t u0 = (uint32_t)__half_as_ushort(__float2half_rn(f0));
    uint32_t u1 = (uint32_t)__half_as_ushort(__float2half_rn(f1));
    return u0 | (u1 << 16);
}
__device__ __forceinline__ void split_h(float v, f16& h, f16& l) {
    h = __float2half_rn(v);
    l = __float2half_rn(v - __half2float(h));
}

// ---------------- GroupNorm statistics --------------------------------------
__global__ void gn_stats(const float* __restrict__ x) {
    int bg = blockIdx.x;
    const float* px = x + (size_t)bg * GN_ELEMS;
    int tid = threadIdx.x;
    float s = 0.f, ss = 0.f;
    for (int i = tid; i < GN_ELEMS; i += 256) {
        float v = px[i];
        s += v; ss += v * v;
    }
    for (int o = 16; o; o >>= 1) {
        s  += __shfl_xor_sync(0xffffffffu, s, o);
        ss += __shfl_xor_sync(0xffffffffu, ss, o);
    }
    __shared__ float sm_s[8], sm_ss[8];
    int lane = tid & 31, warp = tid >> 5;
    if (lane == 0) { sm_s[warp] = s; sm_ss[warp] = ss; }
    __syncthreads();
    if (tid == 0) {
        float ts = 0.f, tss = 0.f;
        for (int i = 0; i < 8; i++) { ts += sm_s[i]; tss += sm_ss[i]; }
        float mean = ts * (1.0f / GN_ELEMS);
        float var  = tss * (1.0f / GN_ELEMS) - mean * mean;
        g_mean[bg] = mean;
        g_rstd[bg] = rsqrtf(var + 1e-6f);
    }
}

// ---------------- zero the rowsum array --------------------------------------
__global__ void zero_rs(float* __restrict__ rs) {
    rs[blockIdx.x * 256 + threadIdx.x] = 0.f;
}

// ---------------- GroupNorm apply + transpose + fp16 split -------------------
__global__ void gn_apply(const float* __restrict__ x,
                         const float* __restrict__ w,
                         const float* __restrict__ b,
                         f16* __restrict__ hh, f16* __restrict__ hl) {
    __shared__ float tile[32][33];
    int bb = blockIdx.z, c0 = blockIdx.y * 32, n0 = blockIdx.x * 32;
    int tx = threadIdx.x, ty = threadIdx.y;
#pragma unroll
    for (int i = 0; i < 4; i++) {
        int c = c0 + ty + i * 8;
        int n = n0 + tx;
        float v = x[((size_t)bb * CCH + c) * NPIX + n];
        int g = c >> 3;
        v = (v - g_mean[bb * NGRP + g]) * g_rstd[bb * NGRP + g] * w[c] + b[c];
        tile[ty + i * 8][tx] = v;
    }
    __syncthreads();
#pragma unroll
    for (int i = 0; i < 4; i++) {
        int n = n0 + ty + i * 8;
        int c = c0 + tx;
        float v = tile[tx][ty + i * 8];
        size_t idx = ((size_t)bb * NPIX + n) * CCH + c;
        f16 h, l; split_h(v, h, l);
        hh[idx] = h;
        hl[idx] = l;
    }
}

// ---------------- split 4 weight matrices ------------------------------------
__global__ void split_weights(const float* __restrict__ q, const float* __restrict__ k,
                              const float* __restrict__ v, const float* __restrict__ o,
                              f16* __restrict__ wh, f16* __restrict__ wl) {
    int i = blockIdx.x * 256 + threadIdx.x;
    int mat = i >> 16, off = i & 65535;
    const float* src = (mat == 0) ? q : (mat == 1) ? k : (mat == 2) ? v : o;
    float val = src[off];
    f16 h, l; split_h(val, h, l);
    wh[i] = h;
    wl[i] = l;
}

// ---------------- transpose v: [B,N,C] f32 -> [B,C,N] single fp16 ------------
__global__ void v_transpose(const float* __restrict__ v, f16* __restrict__ t) {
    __shared__ float tile[32][33];
    int bb = blockIdx.z, c0 = blockIdx.y * 32, n0 = blockIdx.x * 32;
    int tx = threadIdx.x, ty = threadIdx.y;
#pragma unroll
    for (int i = 0; i < 4; i++) {
        int n = n0 + ty + i * 8;
        tile[ty + i * 8][tx] = v[((size_t)bb * NPIX + n) * CCH + c0 + tx];
    }
    __syncthreads();
#pragma unroll
    for (int i = 0; i < 4; i++) {
        int c = c0 + ty + i * 8;
        int n = n0 + tx;
        t[((size_t)bb * CCH + c) * NPIX + n] = __float2half_rn(tile[tx][ty + i * 8]);
    }
}

// ---------------- mma.sync GEMM: C = A @ B^T (+bias) -------------------------
// A [M,K] fp16 row-major (hi [+lo if NTA=2]); B [N,K] fp16 (hi [+lo if NTB=2]).
// MMAs/k16: NTA=2,NTB=2 -> 3 (AhBh+AlBh+AhBl); NTA=2,NTB=1 -> 2; NTA=1,NTB=1 -> 1.
// Stages: NTERMS=4 -> 2, NTERMS=3 -> 3, NTERMS=2 -> 4 (80KB smem, 2 CTAs/SM).
// EMODE 0: fp32 out (+bias)
// EMODE 1: fp16 hi/lo out (+bias); if rs: rows scaled by 1/rs[m]
// EMODE 2: exp(acc*SCALE-ESHIFT) -> fp16 single, rowsums atomically added to rs
// EMODE 3: fp16 single out (+bias)
#define RS     40                   // padded row stride (elems)
#define TERMSZ (128 * RS)           // 5120 elems = 10240 B
#define SMEMSZ 81920

template <int EMODE, int NTA, int NTB>
__global__ void __launch_bounds__(256, 2)
mma_gemm(const f16* __restrict__ Ah, const f16* __restrict__ Al,
         const f16* __restrict__ Bh, const f16* __restrict__ Bl,
         const float* __restrict__ bias,
         float* __restrict__ Cf, f16* __restrict__ Ch, f16* __restrict__ Cl,
         float* rs,
         int M, int N, int K, long sA, long sB, long sC) {
    constexpr int NTERMS = NTA + NTB;
    constexpr int NSTAGE = (NTERMS == 2) ? 4 : (NTERMS == 3) ? 3 : 2;
    constexpr int STAGEELEMS = NTERMS * TERMSZ;
    extern __shared__ f16 sm[];
    int tid = threadIdx.x, lane = tid & 31, wid = tid >> 5;
    Ah += (size_t)blockIdx.z * sA;
    if (NTA == 2) Al += (size_t)blockIdx.z * sA;
    Bh += (size_t)blockIdx.z * sB;
    if (NTB == 2) Bl += (size_t)blockIdx.z * sB;
    if (rs) rs += (size_t)blockIdx.z * M;
    size_t coff = (size_t)blockIdx.z * sC;
    int tm = blockIdx.y * 128, tn = blockIdx.x * 128;
    int nk = K >> 5;

    int wm0 = (wid & 1) * 64;
    int wn0 = (wid >> 1) * 32;
    int gr = lane >> 2, tc = lane & 3;

    int lr = lane & 7, lm = lane >> 3;
    uint32_t rowA = (uint32_t)(wm0 + (lm & 1) * 8 + lr);
    uint32_t kAoff = (uint32_t)((lm >> 1) * 8);
    uint32_t rowB = (uint32_t)(wn0 + (lm >> 1) * 8 + lr);
    uint32_t kBoff = (uint32_t)((lm & 1) * 8);

    uint32_t sb = smem_u32(sm);

    float acc[4][4][4];
#pragma unroll
    for (int i = 0; i < 4; i++)
#pragma unroll
        for (int j = 0; j < 4; j++)
#pragma unroll
            for (int r = 0; r < 4; r++) acc[i][j][r] = 0.f;

    auto load_stage = [&](int chunk) {
        int st = chunk % NSTAGE;
        int kb = chunk * 32;
#pragma unroll
        for (int i = 0; i < NTERMS * 2; i++) {
            int c = tid + i * 256;
            int t = c >> 9;                 // term index: A terms then B terms
            int idx = c & 511;
            int row = idx >> 2, g = idx & 3;
            const f16* src = (t < NTA) ? ((t == 0) ? Ah : Al)
                                       : ((t == NTA) ? Bh : Bl);
            int rb = (t < NTA) ? tm : tn;
            uint32_t dst = sb + (uint32_t)(st * STAGEELEMS + t * TERMSZ + row * RS + g * 8) * 2;
            cp_async16(dst, src + ((size_t)(rb + row) * K + kb + g * 8));
        }
        asm volatile("cp.async.commit_group;" ::: "memory");
    };

#pragma unroll
    for (int c = 0; c < NSTAGE; c++)
        if (c < nk) load_stage(c);

    for (int kt = 0; kt < nk; kt++) {
        // ensure chunk kt's group is complete: outstanding = min(NSTAGE-1, nk-1-kt)
        if (kt + NSTAGE <= nk)      cp_wait<NSTAGE - 1>();
        else if (kt == nk - 1)      cp_wait<0>();
        else if (kt == nk - 2)      cp_wait<(NSTAGE >= 2) ? 1 : 0>();
        else if (kt == nk - 3)      cp_wait<(NSTAGE >= 3) ? 2 : 0>();
        __syncthreads();

        uint32_t stage = sb + (uint32_t)((kt % NSTAGE) * STAGEELEMS) * 2;
        uint32_t sAh = stage;
        uint32_t sAl = stage + TERMSZ * 2;
        uint32_t sBh = stage + NTA * TERMSZ * 2;
        uint32_t sBl = stage + (NTA + 1) * TERMSZ * 2;

#pragma unroll
        for (int kk = 0; kk < 2; kk++) {
            uint32_t k0 = (uint32_t)(kk * 16);
            uint32_t bh[4][2], bl[4][2];
#pragma unroll
            for (int p = 0; p < 2; p++) {
                uint32_t boff = ((rowB + p * 16) * RS + k0 + kBoff) * 2;
                ldsm_x4(sBh + boff, &bh[p * 2][0]);
                if (NTB == 2) ldsm_x4(sBl + boff, &bl[p * 2][0]);
            }
#pragma unroll
            for (int mi = 0; mi < 4; mi++) {
                uint32_t aoff = ((rowA + mi * 16) * RS + k0 + kAoff) * 2;
                uint32_t ah[4], al[4];
                ldsm_x4(sAh + aoff, ah);
                if (NTA == 2) ldsm_x4(sAl + aoff, al);
#pragma unroll
                for (int ni = 0; ni < 4; ni++) {
                    mma16816(acc[mi][ni], ah, bh[ni]);
                    if (NTA == 2) mma16816(acc[mi][ni], al, bh[ni]);
                    if (NTB == 2) mma16816(acc[mi][ni], ah, bl[ni]);
                }
            }
        }
        __syncthreads();
        if (kt + NSTAGE < nk) load_stage(kt + NSTAGE);
    }

    // ---------------- epilogue ----------------
    if (EMODE == 2) {
#pragma unroll
        for (int mi = 0; mi < 4; mi++) {
            float s0 = 0.f, s1 = 0.f;
#pragma unroll
            for (int ni = 0; ni < 4; ni++) {
                acc[mi][ni][0] = __expf(acc[mi][ni][0] * SCALE - ESHIFT);
                acc[mi][ni][1] = __expf(acc[mi][ni][1] * SCALE - ESHIFT);
                acc[mi][ni][2] = __expf(acc[mi][ni][2] * SCALE - ESHIFT);
                acc[mi][ni][3] = __expf(acc[mi][ni][3] * SCALE - ESHIFT);
                s0 += acc[mi][ni][0] + acc[mi][ni][1];
                s1 += acc[mi][ni][2] + acc[mi][ni][3];
            }
            s0 += __shfl_xor_sync(0xffffffffu, s0, 1);
            s0 += __shfl_xor_sync(0xffffffffu, s0, 2);
            s1 += __shfl_xor_sync(0xffffffffu, s1, 1);
            s1 += __shfl_xor_sync(0xffffffffu, s1, 2);
            if (tc == 0) {
                int r = tm + wm0 + mi * 16 + gr;
                atomicAdd(&rs[r], s0);
                atomicAdd(&rs[r + 8], s1);
            }
        }
    }

#pragma unroll
    for (int mi = 0; mi < 4; mi++) {
        float inv0 = 1.f, inv1 = 1.f;
        if (EMODE == 1 && rs) {
            int r = tm + wm0 + mi * 16 + gr;
            inv0 = 1.0f / rs[r];
            inv1 = 1.0f / rs[r + 8];
        }
#pragma unroll
        for (int ni = 0; ni < 4; ni++) {
            int m = tm + wm0 + mi * 16 + gr;
            int n = tn + wn0 + ni * 8 + tc * 2;
            float b0v = (EMODE != 2 && bias) ? bias[n]     : 0.f;
            float b1v = (EMODE != 2 && bias) ? bias[n + 1] : 0.f;
            float c0 = acc[mi][ni][0] * inv0 + b0v, c1 = acc[mi][ni][1] * inv0 + b1v;
            float c2 = acc[mi][ni][2] * inv1 + b0v, c3 = acc[mi][ni][3] * inv1 + b1v;
            if (EMODE == 0) {
                float2 v0 = {c0, c1}, v1 = {c2, c3};
                *(float2*)&Cf[coff + (size_t)m * N + n]       = v0;
                *(float2*)&Cf[coff + (size_t)(m + 8) * N + n] = v1;
            } else if (EMODE == 2 || EMODE == 3) {
                *(uint32_t*)&Ch[coff + (size_t)m * N + n]       = pack_h2(c0, c1);
                *(uint32_t*)&Ch[coff + (size_t)(m + 8) * N + n] = pack_h2(c2, c3);
            } else {
                f16 h0 = __float2half_rn(c0), h1 = __float2half_rn(c1);
                f16 h2 = __float2half_rn(c2), h3 = __float2half_rn(c3);
                uint32_t hi0 = (uint32_t)__half_as_ushort(h0) |
                               ((uint32_t)__half_as_ushort(h1) << 16);
                uint32_t hi1 = (uint32_t)__half_as_ushort(h2) |
                               ((uint32_t)__half_as_ushort(h3) << 16);
                uint32_t lo0 = pack_h2(c0 - __half2float(h0), c1 - __half2float(h1));
                uint32_t lo1 = pack_h2(c2 - __half2float(h2), c3 - __half2float(h3));
                *(uint32_t*)&Ch[coff + (size_t)m * N + n]       = hi0;
                *(uint32_t*)&Ch[coff + (size_t)(m + 8) * N + n] = hi1;
                *(uint32_t*)&Cl[coff + (size_t)m * N + n]       = lo0;
                *(uint32_t*)&Cl[coff + (size_t)(m + 8) * N + n] = lo1;
            }
        }
    }
}

// ---------------- final: y = (x + tmp^T) * 1/sqrt(2) -------------------------
__global__ void final_residual(const float* __restrict__ x,
                               const float* __restrict__ tmp,
                               float* __restrict__ y) {
    __shared__ float tile[32][33];
    int bb = blockIdx.z, c0 = blockIdx.y * 32, n0 = blockIdx.x * 32;
    int tx = threadIdx.x, ty = threadIdx.y;
#pragma unroll
    for (int i = 0; i < 4; i++) {
        int n = n0 + ty + i * 8;
        tile[ty + i * 8][tx] = tmp[((size_t)bb * NPIX + n) * CCH + c0 + tx];
    }
    __syncthreads();
#pragma unroll
    for (int i = 0; i < 4; i++) {
        int c = c0 + ty + i * 8;
        int n = n0 + tx;
        size_t idx = ((size_t)bb * CCH + c) * NPIX + n;
        y[idx] = (x[idx] + tile[tx][ty + i * 8]) * INV_SQRT2;
    }
}

// ---------------- launch ------------------------------------------------------
extern "C" void kernel_launch(void* const* d_in, const int* in_sizes, int n_in,
                              void* d_out, int out_size) {
    const float* x  = (const float*)d_in[0];
    const float* gw = (const float*)d_in[1];
    const float* gb = (const float*)d_in[2];
    const float* Wq = (const float*)d_in[3];
    const float* bq = (const float*)d_in[4];
    const float* Wk = (const float*)d_in[5];
    const float* bk = (const float*)d_in[6];
    const float* Wv = (const float*)d_in[7];
    const float* bv = (const float*)d_in[8];
    const float* Wo = (const float*)d_in[9];
    const float* bo = (const float*)d_in[10];
    float* y = (float*)d_out;

    cudaFuncSetAttribute(mma_gemm<0, 2, 2>, cudaFuncAttributeMaxDynamicSharedMemorySize, SMEMSZ);
    cudaFuncSetAttribute(mma_gemm<3, 2, 2>, cudaFuncAttributeMaxDynamicSharedMemorySize, SMEMSZ);
    cudaFuncSetAttribute(mma_gemm<2, 1, 1>, cudaFuncAttributeMaxDynamicSharedMemorySize, SMEMSZ);
    cudaFuncSetAttribute(mma_gemm<1, 1, 1>, cudaFuncAttributeMaxDynamicSharedMemorySize, SMEMSZ);

    f16 *hs_h, *hs_l, *q1, *k1, *vt, *p1, *ao_h, *ao_l, *w_h, *w_l;
    float *v, *tmp, *rsum;
    cudaGetSymbolAddress((void**)&hs_h, g_hs_h);
    cudaGetSymbolAddress((void**)&hs_l, g_hs_l);
    cudaGetSymbolAddress((void**)&q1,   g_q);
    cudaGetSymbolAddress((void**)&k1,   g_k);
    cudaGetSymbolAddress((void**)&v,    g_v);
    cudaGetSymbolAddress((void**)&vt,   g_vt);
    cudaGetSymbolAddress((void**)&p1,   g_p);
    cudaGetSymbolAddress((void**)&ao_h, g_ao_h);
    cudaGetSymbolAddress((void**)&ao_l, g_ao_l);
    cudaGetSymbolAddress((void**)&tmp,  g_tmp);
    cudaGetSymbolAddress((void**)&w_h,  g_w_h);
    cudaGetSymbolAddress((void**)&w_l,  g_w_l);
    cudaGetSymbolAddress((void**)&rsum, g_rowsum);

    const long NC = (long)NPIX * CCH;
    const long NN = (long)NPIX * NPIX;
    const int  MALL = BATCH * NPIX;   // 16384

    gn_stats<<<BATCH * NGRP, 256>>>(x);
    zero_rs<<<(BATCH * NPIX) / 256, 256>>>(rsum);
    gn_apply<<<dim3(NPIX / 32, CCH / 32, BATCH), dim3(32, 8)>>>(x, gw, gb, hs_h, hs_l);
    split_weights<<<1024, 256>>>(Wq, Wk, Wv, Wo, w_h, w_l);

    // Q projection -> fp16 single
    mma_gemm<3, 2, 2><<<dim3(2, MALL / 128, 1), 256, SMEMSZ>>>(
        hs_h, hs_l, w_h, w_l, bq, nullptr, q1, nullptr, nullptr, MALL, CCH, CCH, 0, 0, 0);
    // K projection -> fp16 single
    mma_gemm<3, 2, 2><<<dim3(2, MALL / 128, 1), 256, SMEMSZ>>>(
        hs_h, hs_l, w_h + 65536, w_l + 65536, bk, nullptr, k1, nullptr, nullptr, MALL, CCH, CCH, 0, 0, 0);
    // V projection -> fp32, then transpose -> fp16 single [B,C,N]
    mma_gemm<0, 2, 2><<<dim3(2, MALL / 128, 1), 256, SMEMSZ>>>(
        hs_h, hs_l, w_h + 131072, w_l + 131072, bv, v, nullptr, nullptr, nullptr, MALL, CCH, CCH, 0, 0, 0);
    v_transpose<<<dim3(NPIX / 32, CCH / 32, BATCH), dim3(32, 8)>>>(v, vt);

    // S = Q @ K^T (1 MMA/k16): epilogue exp(+shift) + rowsums -> fp16 single P
    mma_gemm<2, 1, 1><<<dim3(32, 32, BATCH), 256, SMEMSZ>>>(
        q1, nullptr, k1, nullptr, nullptr, nullptr, p1, nullptr, rsum,
        NPIX, NPIX, CCH, NC, NC, NN);

    // AO = (P @ V) / rowsum (1 MMA/k16) -> fp16 hi/lo
    mma_gemm<1, 1, 1><<<dim3(2, 32, BATCH), 256, SMEMSZ>>>(
        p1, nullptr, vt, nullptr, nullptr, nullptr, ao_h, ao_l, rsum,
        NPIX, CCH, NPIX, NN, NC, NC);

    // O projection -> fp32 (3-term, accurate)
    mma_gemm<0, 2, 2><<<dim3(2, MALL / 128, 1), 256, SMEMSZ>>>(
        ao_h, ao_l, w_h + 196608, w_l + 196608, bo, tmp, nullptr, nullptr, nullptr,
        MALL, CCH, CCH, 0, 0, 0);

    final_residual<<<dim3(NPIX / 32, CCH / 32, BATCH), dim3(32, 8)>>>(x, tmp, y);
}

// round 9
// speedup vs baseline: 5.0187x; 1.1226x over previous
#include <cuda_runtime.h>
#include <cuda_fp16.h>
#include <math_constants.h>
#include <cstdint>

typedef __half f16;

#define BATCH 4
#define CCH   256
#define NPIX  4096
#define NGRP  32
#define GN_ELEMS (8 * NPIX)
#define SCALE 0.0625f
#define ESHIFT 4.0f
#define INV_SQRT2 0.70710678118654752f

#define NELT (BATCH * NPIX * CCH)            // 4,194,304
#define NNELT ((size_t)BATCH * NPIX * NPIX)  // 67,108,864

// ---------------- scratch (device globals) ---------------------------------
__device__ f16   g_hs [NELT];                    // GN output, single fp16
__device__ f16   g_q  [NELT];
__device__ f16   g_k  [NELT];
__device__ f16   g_v16[NELT];                    // V in [B,N,C] fp16
__device__ f16   g_vt [NELT];                    // V^T in [B,C,N] fp16
__device__ f16   g_p  [NNELT];                   // unnormalized shifted exp
__device__ f16   g_ao [NELT];                    // normalized attn output
__device__ float g_tmp[NELT];
__device__ f16   g_w  [4 * CCH * CCH];           // Wq,Wk,Wv,Wo single fp16
__device__ float g_mean[BATCH * NGRP], g_rstd[BATCH * NGRP];
__device__ float g_rowsum[BATCH * NPIX];

// ---------------- helpers ----------------------------------------------------
__device__ __forceinline__ uint32_t smem_u32(const void* p) {
    uint32_t a;
    asm("{ .reg .u64 t; cvta.to.shared.u64 t, %1; cvt.u32.u64 %0, t; }"
        : "=r"(a) : "l"(p));
    return a;
}
__device__ __forceinline__ void cp_async16(uint32_t dst, const void* src) {
    asm volatile("cp.async.cg.shared.global [%0], [%1], 16;" :: "r"(dst), "l"(src));
}
template <int N>
__device__ __forceinline__ void cp_wait() {
    asm volatile("cp.async.wait_group %0;" :: "n"(N) : "memory");
}
__device__ __forceinline__ void ldsm_x4(uint32_t addr, uint32_t* r) {
    asm volatile("ldmatrix.sync.aligned.m8n8.x4.shared.b16 {%0,%1,%2,%3}, [%4];"
                 : "=r"(r[0]), "=r"(r[1]), "=r"(r[2]), "=r"(r[3]) : "r"(addr));
}
__device__ __forceinline__ void mma16816(float* c, const uint32_t* a, const uint32_t* b) {
    asm volatile(
        "mma.sync.aligned.m16n8k16.row.col.f32.f16.f16.f32 "
        "{%0,%1,%2,%3}, {%4,%5,%6,%7}, {%8,%9}, {%0,%1,%2,%3};"
        : "+f"(c[0]), "+f"(c[1]), "+f"(c[2]), "+f"(c[3])
        : "r"(a[0]), "r"(a[1]), "r"(a[2]), "r"(a[3]), "r"(b[0]), "r"(b[1]));
}
__device__ __forceinline__ uint32_t pack_h2(float f0, float f1) {
    uint32_t u0 = (uint32_t)__half_as_ushort(__float2half_rn(f0));
    uint32_t u1 = (uint32_t)__half_as_ushort(__float2half_rn(f1));
    return u0 | (u1 << 16);
}

// ---------------- GroupNorm statistics --------------------------------------
__global__ void gn_stats(const float* __restrict__ x) {
    int bg = blockIdx.x;
    const float* px = x + (size_t)bg * GN_ELEMS;
    int tid = threadIdx.x;
    float s = 0.f, ss = 0.f;
    for (int i = tid; i < GN_ELEMS; i += 256) {
        float v = px[i];
        s += v; ss += v * v;
    }
    for (int o = 16; o; o >>= 1) {
        s  += __shfl_xor_sync(0xffffffffu, s, o);
        ss += __shfl_xor_sync(0xffffffffu, ss, o);
    }
    __shared__ float sm_s[8], sm_ss[8];
    int lane = tid & 31, warp = tid >> 5;
    if (lane == 0) { sm_s[warp] = s; sm_ss[warp] = ss; }
    __syncthreads();
    if (tid == 0) {
        float ts = 0.f, tss = 0.f;
        for (int i = 0; i < 8; i++) { ts += sm_s[i]; tss += sm_ss[i]; }
        float mean = ts * (1.0f / GN_ELEMS);
        float var  = tss * (1.0f / GN_ELEMS) - mean * mean;
        g_mean[bg] = mean;
        g_rstd[bg] = rsqrtf(var + 1e-6f);
    }
}

// ---------------- zero the rowsum array --------------------------------------
__global__ void zero_rs(float* __restrict__ rs) {
    rs[blockIdx.x * 256 + threadIdx.x] = 0.f;
}

// ---------------- GroupNorm apply + transpose -> single fp16 -----------------
__global__ void gn_apply(const float* __restrict__ x,
                         const float* __restrict__ w,
                         const float* __restrict__ b,
                         f16* __restrict__ hs) {
    __shared__ float tile[32][33];
    int bb = blockIdx.z, c0 = blockIdx.y * 32, n0 = blockIdx.x * 32;
    int tx = threadIdx.x, ty = threadIdx.y;
#pragma unroll
    for (int i = 0; i < 4; i++) {
        int c = c0 + ty + i * 8;
        int n = n0 + tx;
        float v = x[((size_t)bb * CCH + c) * NPIX + n];
        int g = c >> 3;
        v = (v - g_mean[bb * NGRP + g]) * g_rstd[bb * NGRP + g] * w[c] + b[c];
        tile[ty + i * 8][tx] = v;
    }
    __syncthreads();
#pragma unroll
    for (int i = 0; i < 4; i++) {
        int n = n0 + ty + i * 8;
        int c = c0 + tx;
        hs[((size_t)bb * NPIX + n) * CCH + c] = __float2half_rn(tile[tx][ty + i * 8]);
    }
}

// ---------------- convert 4 weight matrices to fp16 --------------------------
__global__ void conv_weights(const float* __restrict__ q, const float* __restrict__ k,
                             const float* __restrict__ v, const float* __restrict__ o,
                             f16* __restrict__ w) {
    int i = blockIdx.x * 256 + threadIdx.x;
    int mat = i >> 16, off = i & 65535;
    const float* src = (mat == 0) ? q : (mat == 1) ? k : (mat == 2) ? v : o;
    w[i] = __float2half_rn(src[off]);
}

// ---------------- transpose v: [B,N,C] fp16 -> [B,C,N] fp16 ------------------
__global__ void v_transpose(const f16* __restrict__ v, f16* __restrict__ t) {
    __shared__ f16 tile[32][34];
    int bb = blockIdx.z, c0 = blockIdx.y * 32, n0 = blockIdx.x * 32;
    int tx = threadIdx.x, ty = threadIdx.y;
#pragma unroll
    for (int i = 0; i < 4; i++) {
        int n = n0 + ty + i * 8;
        tile[ty + i * 8][tx] = v[((size_t)bb * NPIX + n) * CCH + c0 + tx];
    }
    __syncthreads();
#pragma unroll
    for (int i = 0; i < 4; i++) {
        int c = c0 + ty + i * 8;
        int n = n0 + tx;
        t[((size_t)bb * CCH + c) * NPIX + n] = tile[tx][ty + i * 8];
    }
}

// ---------------- mma.sync GEMM: C = A @ B^T (+bias) -------------------------
// A [M,K] fp16 row-major, B [N,K] fp16 row-major; 1 MMA per k16.
// EMODE 0: fp32 out (+bias)
// EMODE 2: exp(acc*SCALE-ESHIFT) -> fp16 single, rowsums atomically added to rs
// EMODE 3: fp16 single out (+bias); if rs: rows scaled by 1/rs[m]
// 128x128x32 tile, 4-stage cp.async pipeline, 8 warps, 2 CTAs/SM, ldmatrix.
#define RS     40                   // padded row stride (elems)
#define TERMSZ (128 * RS)           // 5120 elems = 10240 B
#define SMEMSZ 81920                // 4 stages x 2 arrays x 10240 B

template <int EMODE>
__global__ void __launch_bounds__(256, 2)
mma_gemm(const f16* __restrict__ A, const f16* __restrict__ B,
         const float* __restrict__ bias,
         float* __restrict__ Cf, f16* __restrict__ Ch,
         float* rs,
         int M, int N, int K, long sA, long sB, long sC) {
    constexpr int NSTAGE = 4;
    constexpr int STAGEELEMS = 2 * TERMSZ;
    extern __shared__ f16 sm[];
    int tid = threadIdx.x, lane = tid & 31, wid = tid >> 5;
    A += (size_t)blockIdx.z * sA;
    B += (size_t)blockIdx.z * sB;
    if (rs) rs += (size_t)blockIdx.z * M;
    size_t coff = (size_t)blockIdx.z * sC;
    int tm = blockIdx.y * 128, tn = blockIdx.x * 128;
    int nk = K >> 5;

    int wm0 = (wid & 1) * 64;
    int wn0 = (wid >> 1) * 32;
    int gr = lane >> 2, tc = lane & 3;

    int lr = lane & 7, lm = lane >> 3;
    uint32_t rowA = (uint32_t)(wm0 + (lm & 1) * 8 + lr);
    uint32_t kAoff = (uint32_t)((lm >> 1) * 8);
    uint32_t rowB = (uint32_t)(wn0 + (lm >> 1) * 8 + lr);
    uint32_t kBoff = (uint32_t)((lm & 1) * 8);

    uint32_t sb = smem_u32(sm);

    float acc[4][4][4];
#pragma unroll
    for (int i = 0; i < 4; i++)
#pragma unroll
        for (int j = 0; j < 4; j++)
#pragma unroll
            for (int r = 0; r < 4; r++) acc[i][j][r] = 0.f;

    auto load_stage = [&](int chunk) {
        int st = chunk % NSTAGE;
        int kb = chunk * 32;
#pragma unroll
        for (int i = 0; i < 4; i++) {
            int c = tid + i * 256;          // 0..1023
            int t = c >> 9;                 // 0 = A, 1 = B
            int idx = c & 511;
            int row = idx >> 2, g = idx & 3;
            const f16* src = (t == 0) ? A : B;
            int rb = (t == 0) ? tm : tn;
            uint32_t dst = sb + (uint32_t)(st * STAGEELEMS + t * TERMSZ + row * RS + g * 8) * 2;
            cp_async16(dst, src + ((size_t)(rb + row) * K + kb + g * 8));
        }
        asm volatile("cp.async.commit_group;" ::: "memory");
    };

#pragma unroll
    for (int c = 0; c < NSTAGE; c++)
        if (c < nk) load_stage(c);

    for (int kt = 0; kt < nk; kt++) {
        if (kt + NSTAGE <= nk)      cp_wait<NSTAGE - 1>();
        else if (kt == nk - 1)      cp_wait<0>();
        else if (kt == nk - 2)      cp_wait<1>();
        else if (kt == nk - 3)      cp_wait<2>();
        __syncthreads();

        uint32_t stage = sb + (uint32_t)((kt % NSTAGE) * STAGEELEMS) * 2;
        uint32_t sA = stage;
        uint32_t sB = stage + TERMSZ * 2;

#pragma unroll
        for (int kk = 0; kk < 2; kk++) {
            uint32_t k0 = (uint32_t)(kk * 16);
            uint32_t bf[4][2];
#pragma unroll
            for (int p = 0; p < 2; p++) {
                uint32_t boff = ((rowB + p * 16) * RS + k0 + kBoff) * 2;
                ldsm_x4(sB + boff, &bf[p * 2][0]);
            }
#pragma unroll
            for (int mi = 0; mi < 4; mi++) {
                uint32_t aoff = ((rowA + mi * 16) * RS + k0 + kAoff) * 2;
                uint32_t af[4];
                ldsm_x4(sA + aoff, af);
#pragma unroll
                for (int ni = 0; ni < 4; ni++)
                    mma16816(acc[mi][ni], af, bf[ni]);
            }
        }
        __syncthreads();
        if (kt + NSTAGE < nk) load_stage(kt + NSTAGE);
    }

    // ---------------- epilogue ----------------
    if (EMODE == 2) {
#pragma unroll
        for (int mi = 0; mi < 4; mi++) {
            float s0 = 0.f, s1 = 0.f;
#pragma unroll
            for (int ni = 0; ni < 4; ni++) {
                acc[mi][ni][0] = __expf(acc[mi][ni][0] * SCALE - ESHIFT);
                acc[mi][ni][1] = __expf(acc[mi][ni][1] * SCALE - ESHIFT);
                acc[mi][ni][2] = __expf(acc[mi][ni][2] * SCALE - ESHIFT);
                acc[mi][ni][3] = __expf(acc[mi][ni][3] * SCALE - ESHIFT);
                s0 += acc[mi][ni][0] + acc[mi][ni][1];
                s1 += acc[mi][ni][2] + acc[mi][ni][3];
            }
            s0 += __shfl_xor_sync(0xffffffffu, s0, 1);
            s0 += __shfl_xor_sync(0xffffffffu, s0, 2);
            s1 += __shfl_xor_sync(0xffffffffu, s1, 1);
            s1 += __shfl_xor_sync(0xffffffffu, s1, 2);
            if (tc == 0) {
                int r = tm + wm0 + mi * 16 + gr;
                atomicAdd(&rs[r], s0);
                atomicAdd(&rs[r + 8], s1);
            }
        }
    }

#pragma unroll
    for (int mi = 0; mi < 4; mi++) {
        float inv0 = 1.f, inv1 = 1.f;
        if (EMODE == 3 && rs) {
            int r = tm + wm0 + mi * 16 + gr;
            inv0 = 1.0f / rs[r];
            inv1 = 1.0f / rs[r + 8];
        }
#pragma unroll
        for (int ni = 0; ni < 4; ni++) {
            int m = tm + wm0 + mi * 16 + gr;
            int n = tn + wn0 + ni * 8 + tc * 2;
            float b0v = (EMODE != 2 && bias) ? bias[n]     : 0.f;
            float b1v = (EMODE != 2 && bias) ? bias[n + 1] : 0.f;
            float c0 = acc[mi][ni][0] * inv0 + b0v, c1 = acc[mi][ni][1] * inv0 + b1v;
            float c2 = acc[mi][ni][2] * inv1 + b0v, c3 = acc[mi][ni][3] * inv1 + b1v;
            if (EMODE == 0) {
                float2 v0 = {c0, c1}, v1 = {c2, c3};
                *(float2*)&Cf[coff + (size_t)m * N + n]       = v0;
                *(float2*)&Cf[coff + (size_t)(m + 8) * N + n] = v1;
            } else {
                *(uint32_t*)&Ch[coff + (size_t)m * N + n]       = pack_h2(c0, c1);
                *(uint32_t*)&Ch[coff + (size_t)(m + 8) * N + n] = pack_h2(c2, c3);
            }
        }
    }
}

// ---------------- final: y = (x + tmp^T) * 1/sqrt(2) -------------------------
__global__ void final_residual(const float* __restrict__ x,
                               const float* __restrict__ tmp,
                               float* __restrict__ y) {
    __shared__ float tile[32][33];
    int bb = blockIdx.z, c0 = blockIdx.y * 32, n0 = blockIdx.x * 32;
    int tx = threadIdx.x, ty = threadIdx.y;
#pragma unroll
    for (int i = 0; i < 4; i++) {
        int n = n0 + ty + i * 8;
        tile[ty + i * 8][tx] = tmp[((size_t)bb * NPIX + n) * CCH + c0 + tx];
    }
    __syncthreads();
#pragma unroll
    for (int i = 0; i < 4; i++) {
        int c = c0 + ty + i * 8;
        int n = n0 + tx;
        size_t idx = ((size_t)bb * CCH + c) * NPIX + n;
        y[idx] = (x[idx] + tile[tx][ty + i * 8]) * INV_SQRT2;
    }
}

// ---------------- launch ------------------------------------------------------
extern "C" void kernel_launch(void* const* d_in, const int* in_sizes, int n_in,
                              void* d_out, int out_size) {
    const float* x  = (const float*)d_in[0];
    const float* gw = (const float*)d_in[1];
    const float* gb = (const float*)d_in[2];
    const float* Wq = (const float*)d_in[3];
    const float* bq = (const float*)d_in[4];
    const float* Wk = (const float*)d_in[5];
    const float* bk = (const float*)d_in[6];
    const float* Wv = (const float*)d_in[7];
    const float* bv = (const float*)d_in[8];
    const float* Wo = (const float*)d_in[9];
    const float* bo = (const float*)d_in[10];
    float* y = (float*)d_out;

    cudaFuncSetAttribute(mma_gemm<0>, cudaFuncAttributeMaxDynamicSharedMemorySize, SMEMSZ);
    cudaFuncSetAttribute(mma_gemm<2>, cudaFuncAttributeMaxDynamicSharedMemorySize, SMEMSZ);
    cudaFuncSetAttribute(mma_gemm<3>, cudaFuncAttributeMaxDynamicSharedMemorySize, SMEMSZ);

    f16 *hs, *q1, *k1, *v16, *vt, *p1, *ao, *w;
    float *tmp, *rsum;
    cudaGetSymbolAddress((void**)&hs,   g_hs);
    cudaGetSymbolAddress((void**)&q1,   g_q);
    cudaGetSymbolAddress((void**)&k1,   g_k);
    cudaGetSymbolAddress((void**)&v16,  g_v16);
    cudaGetSymbolAddress((void**)&vt,   g_vt);
    cudaGetSymbolAddress((void**)&p1,   g_p);
    cudaGetSymbolAddress((void**)&ao,   g_ao);
    cudaGetSymbolAddress((void**)&tmp,  g_tmp);
    cudaGetSymbolAddress((void**)&w,    g_w);
    cudaGetSymbolAddress((void**)&rsum, g_rowsum);

    const long NC = (long)NPIX * CCH;
    const long NN = (long)NPIX * NPIX;
    const int  MALL = BATCH * NPIX;   // 16384

    gn_stats<<<BATCH * NGRP, 256>>>(x);
    zero_rs<<<(BATCH * NPIX) / 256, 256>>>(rsum);
    gn_apply<<<dim3(NPIX / 32, CCH / 32, BATCH), dim3(32, 8)>>>(x, gw, gb, hs);
    conv_weights<<<1024, 256>>>(Wq, Wk, Wv, Wo, w);

    // Projections (1 MMA/k16): Q, K, V -> fp16 single
    mma_gemm<3><<<dim3(2, MALL / 128, 1), 256, SMEMSZ>>>(
        hs, w, bq, nullptr, q1, nullptr, MALL, CCH, CCH, 0, 0, 0);
    mma_gemm<3><<<dim3(2, MALL / 128, 1), 256, SMEMSZ>>>(
        hs, w + 65536, bk, nullptr, k1, nullptr, MALL, CCH, CCH, 0, 0, 0);
    mma_gemm<3><<<dim3(2, MALL / 128, 1), 256, SMEMSZ>>>(
        hs, w + 131072, bv, nullptr, v16, nullptr, MALL, CCH, CCH, 0, 0, 0);
    v_transpose<<<dim3(NPIX / 32, CCH / 32, BATCH), dim3(32, 8)>>>(v16, vt);

    // S = Q @ K^T: epilogue exp(+shift) + rowsums -> fp16 single P
    mma_gemm<2><<<dim3(32, 32, BATCH), 256, SMEMSZ>>>(
        q1, k1, nullptr, nullptr, p1, rsum, NPIX, NPIX, CCH, NC, NC, NN);

    // AO = (P @ V) / rowsum -> fp16 single
    mma_gemm<3><<<dim3(2, 32, BATCH), 256, SMEMSZ>>>(
        p1, vt, nullptr, nullptr, ao, rsum, NPIX, CCH, NPIX, NN, NC, NC);

    // O projection -> fp32
    mma_gemm<0><<<dim3(2, MALL / 128, 1), 256, SMEMSZ>>>(
        ao, w + 196608, bo, tmp, nullptr, nullptr, MALL, CCH, CCH, 0, 0, 0);

    final_residual<<<dim3(NPIX / 32, CCH / 32, BATCH), dim3(32, 8)>>>(x, tmp, y);
}